// round 1
// baseline (speedup 1.0000x reference)
#include <cuda_runtime.h>
#include <cstdint>

#define BB 2048   // batch
#define NN 512    // codebook
#define KD 8192   // C*T

// ---------------- scratch (no allocations allowed) ----------------
__device__ float g_d2[(size_t)BB * NN];   // 4 MB distance matrix
__device__ float g_yy[BB];
__device__ float g_mm[NN];
__device__ int   g_assign[BB];
__device__ int   g_cnt[NN];
__device__ int   g_off[NN];
__device__ int   g_items[BB];

// ---------------- K1: row sum-of-squares for y (BB rows) and m (NN rows) ----
__global__ __launch_bounds__(256) void k_sumsq(const float* __restrict__ y,
                                               const float* __restrict__ m) {
    int r = blockIdx.x;
    const float* row = (r < BB) ? (y + (size_t)r * KD) : (m + (size_t)(r - BB) * KD);
    const float4* row4 = (const float4*)row;
    float s = 0.f;
    for (int i = threadIdx.x; i < KD / 4; i += 256) {
        float4 v = row4[i];
        s += v.x * v.x + v.y * v.y + v.z * v.z + v.w * v.w;
    }
    __shared__ float sh[256];
    sh[threadIdx.x] = s;
    __syncthreads();
    for (int st = 128; st > 0; st >>= 1) {
        if (threadIdx.x < st) sh[threadIdx.x] += sh[threadIdx.x + st];
        __syncthreads();
    }
    if (threadIdx.x == 0) {
        if (r < BB) g_yy[r] = sh[0];
        else        g_mm[r - BB] = sh[0];
    }
}

// ---------------- K2: d2[b,n] = (yy[b]+mm[n]) - 2*dot(y_b, m_n) -------------
#define BM 128
#define BN 64
#define BK 16

__global__ __launch_bounds__(256) void k_gemm(const float* __restrict__ Y,
                                              const float* __restrict__ M) {
    __shared__ float As[BK][BM];
    __shared__ float Bs[BK][BN];
    const int tid = threadIdx.x;
    const int tx = tid & 15;   // n direction (4 cols each)
    const int ty = tid >> 4;   // b direction (8 rows each)
    const int b0 = blockIdx.y * BM;
    const int n0 = blockIdx.x * BN;

    float acc[8][4];
#pragma unroll
    for (int i = 0; i < 8; i++)
#pragma unroll
        for (int j = 0; j < 4; j++) acc[i][j] = 0.f;

    for (int kk = 0; kk < KD; kk += BK) {
        // load A tile 128x16 (512 float4, 2 per thread), store transposed
#pragma unroll
        for (int t = 0; t < 2; t++) {
            int lin = tid + t * 256;         // 0..511
            int row = lin >> 2;              // 0..127
            int kq  = lin & 3;               // float4 slot in k
            float4 v = *(const float4*)(Y + (size_t)(b0 + row) * KD + kk + kq * 4);
            As[kq * 4 + 0][row] = v.x;
            As[kq * 4 + 1][row] = v.y;
            As[kq * 4 + 2][row] = v.z;
            As[kq * 4 + 3][row] = v.w;
        }
        // load B tile 64x16 (256 float4, 1 per thread), store transposed
        {
            int row = tid >> 2;
            int kq  = tid & 3;
            float4 v = *(const float4*)(M + (size_t)(n0 + row) * KD + kk + kq * 4);
            Bs[kq * 4 + 0][row] = v.x;
            Bs[kq * 4 + 1][row] = v.y;
            Bs[kq * 4 + 2][row] = v.z;
            Bs[kq * 4 + 3][row] = v.w;
        }
        __syncthreads();

        // two-level accumulation: 16-chunk partial, then fold into acc
        float part[8][4];
#pragma unroll
        for (int i = 0; i < 8; i++)
#pragma unroll
            for (int j = 0; j < 4; j++) part[i][j] = 0.f;

#pragma unroll
        for (int k = 0; k < BK; k++) {
            float a[8], bf[4];
            *(float4*)&a[0] = *(const float4*)&As[k][ty * 8];
            *(float4*)&a[4] = *(const float4*)&As[k][ty * 8 + 4];
            *(float4*)&bf[0] = *(const float4*)&Bs[k][tx * 4];
#pragma unroll
            for (int i = 0; i < 8; i++)
#pragma unroll
                for (int j = 0; j < 4; j++) part[i][j] += a[i] * bf[j];
        }
#pragma unroll
        for (int i = 0; i < 8; i++)
#pragma unroll
            for (int j = 0; j < 4; j++) acc[i][j] += part[i][j];
        __syncthreads();
    }

#pragma unroll
    for (int i = 0; i < 8; i++) {
        int b = b0 + ty * 8 + i;
        float yy = g_yy[b];
#pragma unroll
        for (int j = 0; j < 4; j++) {
            int n = n0 + tx * 4 + j;
            // mimic reference association: (yy + mm) - (2 * dot)
            float d2 = __fsub_rn(__fadd_rn(yy, g_mm[n]), __fmul_rn(2.0f, acc[i][j]));
            g_d2[(size_t)b * NN + n] = d2;
        }
    }
}

// ---------------- K3: argmin over NN per row (first-min tie break) ----------
__global__ __launch_bounds__(128) void k_argmin(float* __restrict__ out_assign) {
    int b = blockIdx.x;
    const float* row = g_d2 + (size_t)b * NN;
    float best = 3.4e38f;
    int   bi = 0;
    for (int n = threadIdx.x; n < NN; n += 128) {   // ascending n per thread
        float v = row[n];
        if (v < best) { best = v; bi = n; }
    }
    __shared__ float sv[128];
    __shared__ int   si[128];
    sv[threadIdx.x] = best;
    si[threadIdx.x] = bi;
    __syncthreads();
    for (int st = 64; st > 0; st >>= 1) {
        if (threadIdx.x < st) {
            float v2 = sv[threadIdx.x + st];
            int   i2 = si[threadIdx.x + st];
            if (v2 < sv[threadIdx.x] ||
                (v2 == sv[threadIdx.x] && i2 < si[threadIdx.x])) {
                sv[threadIdx.x] = v2;
                si[threadIdx.x] = i2;
            }
        }
        __syncthreads();
    }
    if (threadIdx.x == 0) {
        g_assign[b]   = si[0];
        out_assign[b] = (float)si[0];
    }
}

// ---------------- K4: stable grouping by centroid (single block) ------------
__global__ __launch_bounds__(512) void k_group(const float* __restrict__ p_in,
                                               float* __restrict__ p_out) {
    __shared__ int sa[BB];
    __shared__ int scnt[NN];
    __shared__ int soff[NN];
    int tid = threadIdx.x;
    for (int i = tid; i < BB; i += 512) sa[i] = g_assign[i];
    scnt[tid] = 0;
    __syncthreads();
    for (int i = tid; i < BB; i += 512) atomicAdd(&scnt[sa[i]], 1);
    __syncthreads();
    if (tid == 0) {
        int run = 0;
        for (int z = 0; z < NN; z++) { soff[z] = run; run += scnt[z]; }
    }
    __syncthreads();
    // per-centroid ordered collection (broadcast reads of sa[i])
    int z = tid;
    int pos = soff[z];
    for (int i = 0; i < BB; i++)
        if (sa[i] == z) g_items[pos++] = i;
    g_cnt[z] = scnt[z];
    g_off[z] = soff[z];
    p_out[z] = p_in[z] + (float)scnt[z];
}

// ---------------- K5: per-centroid sequential EMA chains --------------------
__global__ __launch_bounds__(256) void k_update(const float* __restrict__ Y,
                                                const float* __restrict__ Min,
                                                const float* __restrict__ SDin,
                                                float* __restrict__ out_m,
                                                float* __restrict__ out_sd) {
    int z   = blockIdx.x;
    int tid = threadIdx.x;
    // each thread owns 8 float4 (32 elems), strided for coalescing
    float4 mv[8], sv[8];
    const float4* mrow = (const float4*)(Min  + (size_t)z * KD);
    const float4* srow = (const float4*)(SDin + (size_t)z * KD);
#pragma unroll
    for (int t = 0; t < 8; t++) {
        mv[t] = mrow[tid + t * 256];
        sv[t] = srow[tid + t * 256];
    }
    int cnt = g_cnt[z];
    int off = g_off[z];
    for (int j = 0; j < cnt; j++) {
        int i = g_items[off + j];
        const float4* yrow = (const float4*)(Y + (size_t)i * KD);
#pragma unroll
        for (int t = 0; t < 8; t++) {
            float4 yv = yrow[tid + t * 256];
            float d;
            mv[t].x = mv[t].x * 0.001f + yv.x * 0.999f;
            d = mv[t].x - yv.x; sv[t].x = d * d * 0.001f + sv[t].x * 0.999f;
            mv[t].y = mv[t].y * 0.001f + yv.y * 0.999f;
            d = mv[t].y - yv.y; sv[t].y = d * d * 0.001f + sv[t].y * 0.999f;
            mv[t].z = mv[t].z * 0.001f + yv.z * 0.999f;
            d = mv[t].z - yv.z; sv[t].z = d * d * 0.001f + sv[t].z * 0.999f;
            mv[t].w = mv[t].w * 0.001f + yv.w * 0.999f;
            d = mv[t].w - yv.w; sv[t].w = d * d * 0.001f + sv[t].w * 0.999f;
        }
    }
    float4* mo = (float4*)(out_m  + (size_t)z * KD);
    float4* so = (float4*)(out_sd + (size_t)z * KD);
#pragma unroll
    for (int t = 0; t < 8; t++) {
        mo[tid + t * 256] = mv[t];
        so[tid + t * 256] = sv[t];
    }
}

// ---------------- launch ----------------------------------------------------
extern "C" void kernel_launch(void* const* d_in, const int* in_sizes, int n_in,
                              void* d_out, int out_size) {
    const float* y  = (const float*)d_in[0];   // [BB, KD]
    const float* m  = (const float*)d_in[1];   // [NN, KD]
    const float* sd = (const float*)d_in[2];   // [NN, KD]
    const float* p  = (const float*)d_in[3];   // [NN]

    float* out      = (float*)d_out;
    float* out_m    = out;                                   // NN*KD
    float* out_sd   = out + (size_t)NN * KD;                 // NN*KD
    float* out_p    = out + 2 * (size_t)NN * KD;             // NN
    float* out_asgn = out_p + NN;                            // BB

    k_sumsq<<<BB + NN, 256>>>(y, m);
    dim3 grid(NN / BN, BB / BM);
    k_gemm<<<grid, 256>>>(y, m);
    k_argmin<<<BB, 128>>>(out_asgn);
    k_group<<<1, 512>>>(p, out_p);
    k_update<<<NN, 256>>>(y, m, sd, out_m, out_sd);
}

// round 4
// speedup vs baseline: 1.7296x; 1.7296x over previous
#include <cuda_runtime.h>
#include <cuda_bf16.h>
#include <cstdint>

#define BB 2048   // batch
#define NN 512    // codebook
#define KD 8192   // C*T

// ---------------- device scratch (no allocations allowed) -------------------
__device__ unsigned short g_yhi[(size_t)BB * KD];   // bf16 bits
__device__ unsigned short g_ylo[(size_t)BB * KD];
__device__ unsigned short g_mhi[(size_t)NN * KD];
__device__ unsigned short g_mlo[(size_t)NN * KD];
__device__ float g_d2[(size_t)BB * NN];             // 4 MB distances
__device__ float g_yy[BB];
__device__ float g_mm[NN];
__device__ int   g_assign[BB];
__device__ int   g_cnt[NN];
__device__ int   g_items2[(size_t)NN * BB];

// ---------------- PTX helpers (sm_80-level ISA only) ------------------------
__device__ __forceinline__ uint32_t smem_u32(const void* p) {
    uint32_t a;
    asm("{ .reg .u64 t; cvta.to.shared.u64 t, %1; cvt.u32.u64 %0, t; }" : "=r"(a) : "l"(p));
    return a;
}
__device__ __forceinline__ void cp_async16(uint32_t dst, const void* src) {
    asm volatile("cp.async.cg.shared.global [%0], [%1], 16;" :: "r"(dst), "l"(src));
}
__device__ __forceinline__ void ldm_x4(uint32_t* r, uint32_t addr) {
    asm volatile("ldmatrix.sync.aligned.m8n8.x4.shared.b16 {%0,%1,%2,%3}, [%4];"
                 : "=r"(r[0]), "=r"(r[1]), "=r"(r[2]), "=r"(r[3]) : "r"(addr));
}
__device__ __forceinline__ void mma_bf16(float* d, const uint32_t* a, const uint32_t* b) {
    asm volatile(
        "mma.sync.aligned.m16n8k16.row.col.f32.bf16.bf16.f32 "
        "{%0,%1,%2,%3}, {%4,%5,%6,%7}, {%8,%9}, {%0,%1,%2,%3};"
        : "+f"(d[0]), "+f"(d[1]), "+f"(d[2]), "+f"(d[3])
        : "r"(a[0]), "r"(a[1]), "r"(a[2]), "r"(a[3]), "r"(b[0]), "r"(b[1]));
}

// ---------------- K0: split fp32 -> bf16 hi/lo ------------------------------
__global__ __launch_bounds__(256) void k_convert(const float* __restrict__ y,
                                                 const float* __restrict__ m) {
    const size_t YC = (size_t)BB * KD / 8;
    size_t gid = (size_t)blockIdx.x * 256 + threadIdx.x;
    const float* src;
    unsigned short *hi, *lo;
    size_t e;
    if (gid < YC) { src = y; hi = g_yhi; lo = g_ylo; e = gid * 8; }
    else          { src = m; hi = g_mhi; lo = g_mlo; e = (gid - YC) * 8; }
    float4 v0 = *(const float4*)(src + e);
    float4 v1 = *(const float4*)(src + e + 4);
    float f[8] = {v0.x, v0.y, v0.z, v0.w, v1.x, v1.y, v1.z, v1.w};
    unsigned short h[8], l[8];
#pragma unroll
    for (int i = 0; i < 8; i++) {
        __nv_bfloat16 bh = __float2bfloat16_rn(f[i]);
        float r = f[i] - __bfloat162float(bh);
        __nv_bfloat16 bl = __float2bfloat16_rn(r);
        h[i] = *(unsigned short*)&bh;
        l[i] = *(unsigned short*)&bl;
    }
    *(uint4*)(hi + e) = *(uint4*)h;
    *(uint4*)(lo + e) = *(uint4*)l;
}

// ---------------- K1: row sum-of-squares ------------------------------------
__global__ __launch_bounds__(256) void k_sumsq(const float* __restrict__ y,
                                               const float* __restrict__ m) {
    int r = blockIdx.x;
    const float* row = (r < BB) ? (y + (size_t)r * KD) : (m + (size_t)(r - BB) * KD);
    const float4* row4 = (const float4*)row;
    float s = 0.f;
    for (int i = threadIdx.x; i < KD / 4; i += 256) {
        float4 v = row4[i];
        s += v.x * v.x + v.y * v.y + v.z * v.z + v.w * v.w;
    }
    __shared__ float sh[256];
    sh[threadIdx.x] = s;
    __syncthreads();
    for (int st = 128; st > 0; st >>= 1) {
        if (threadIdx.x < st) sh[threadIdx.x] += sh[threadIdx.x + st];
        __syncthreads();
    }
    if (threadIdx.x == 0) {
        if (r < BB) g_yy[r] = sh[0];
        else        g_mm[r - BB] = sh[0];
    }
}

// ---------------- K2: split-bf16 HMMA distance GEMM -------------------------
// BM=128, BN=64, BK=32, 256 threads = 8 warps laid out 4M x 2N,
// warp tile 32(M) x 32(N). smem rows padded to 80B -> conflict-free ldmatrix.
#define SROW 80
#define A_MAT 10240        // 128*80
#define B_MAT 5120         // 64*80
#define STG   30720        // Ahi+Alo+Bhi+Blo
#define SM_TOTAL (2 * STG)
#define NSTAGES (KD / 32)  // 256

__device__ __forceinline__ void load_stage(uint32_t sb, int buf, int b0, int n0, int k0,
                                           int tid) {
    uint32_t stA = sb + buf * STG;
    uint32_t stB = stA + 2 * A_MAT;
    const unsigned short* ya[2] = {g_yhi, g_ylo};
    const unsigned short* ma[2] = {g_mhi, g_mlo};
#pragma unroll
    for (int t = 0; t < 4; t++) {                 // A: 2 mats x 128 rows x 4 x 16B
        int idx = t * 256 + tid;
        int mat = idx >> 9;
        int rem = idx & 511;
        int row = rem >> 2, ch = rem & 3;
        const void* src = ya[mat] + (size_t)(b0 + row) * KD + k0 + ch * 8;
        cp_async16(stA + mat * A_MAT + row * SROW + ch * 16, src);
    }
#pragma unroll
    for (int t = 0; t < 2; t++) {                 // B: 2 mats x 64 rows x 4 x 16B
        int idx = t * 256 + tid;
        int mat = idx >> 8;
        int rem = idx & 255;
        int row = rem >> 2, ch = rem & 3;
        const void* src = ma[mat] + (size_t)(n0 + row) * KD + k0 + ch * 8;
        cp_async16(stB + mat * B_MAT + row * SROW + ch * 16, src);
    }
    asm volatile("cp.async.commit_group;");
}

__global__ __launch_bounds__(256, 1) void k_gemm() {
    extern __shared__ char smem[];
    const uint32_t sb = smem_u32(smem);
    const int tid = threadIdx.x;
    const int lane = tid & 31;
    const int wid = tid >> 5;
    const int wm = wid >> 1;          // 0..3 -> M offset wm*32
    const int wn = wid & 1;           // 0..1 -> N offset wn*32
    const int b0 = blockIdx.y * 128;
    const int n0 = blockIdx.x * 64;

    float acc[2][4][4];
#pragma unroll
    for (int i = 0; i < 2; i++)
#pragma unroll
        for (int j = 0; j < 4; j++)
#pragma unroll
            for (int c = 0; c < 4; c++) acc[i][j][c] = 0.f;

    load_stage(sb, 0, b0, n0, 0, tid);

    for (int s = 0; s < NSTAGES; s++) {
        if (s + 1 < NSTAGES) {
            load_stage(sb, (s + 1) & 1, b0, n0, (s + 1) * 32, tid);
            asm volatile("cp.async.wait_group 1;" ::: "memory");
        } else {
            asm volatile("cp.async.wait_group 0;" ::: "memory");
        }
        __syncthreads();

        uint32_t stA = sb + (s & 1) * STG;
        uint32_t stB = stA + 2 * A_MAT;

#pragma unroll
        for (int kstep = 0; kstep < 2; kstep++) {
            // A fragments: 2 m-tiles x {hi,lo}
            uint32_t ah[2][4], al[2][4];
#pragma unroll
            for (int mt = 0; mt < 2; mt++) {
                int row = wm * 32 + mt * 16 + (lane & 15);
                int ch = kstep * 2 + (lane >> 4);
                ldm_x4(ah[mt], stA + row * SROW + ch * 16);
                ldm_x4(al[mt], stA + A_MAT + row * SROW + ch * 16);
            }
            // B fragments: 4 n-tiles (8 cols each) x {hi,lo}
            uint32_t bh[4][2], bl[4][2];
#pragma unroll
            for (int p = 0; p < 2; p++) {
                int row = wn * 32 + p * 16 + (lane & 7) + (lane >> 4) * 8;
                int ch = kstep * 2 + ((lane >> 3) & 1);
                uint32_t r4[4];
                ldm_x4(r4, stB + row * SROW + ch * 16);
                bh[p * 2 + 0][0] = r4[0]; bh[p * 2 + 0][1] = r4[1];
                bh[p * 2 + 1][0] = r4[2]; bh[p * 2 + 1][1] = r4[3];
                ldm_x4(r4, stB + B_MAT + row * SROW + ch * 16);
                bl[p * 2 + 0][0] = r4[0]; bl[p * 2 + 0][1] = r4[1];
                bl[p * 2 + 1][0] = r4[2]; bl[p * 2 + 1][1] = r4[3];
            }
#pragma unroll
            for (int mt = 0; mt < 2; mt++)
#pragma unroll
                for (int nt = 0; nt < 4; nt++) {
                    mma_bf16(acc[mt][nt], ah[mt], bh[nt]);   // hi*hi
                    mma_bf16(acc[mt][nt], al[mt], bh[nt]);   // lo*hi
                    mma_bf16(acc[mt][nt], ah[mt], bl[nt]);   // hi*lo
                }
        }
        __syncthreads();
    }

    // epilogue: d2 = (yy+mm) - 2*dot
#pragma unroll
    for (int mt = 0; mt < 2; mt++) {
        int row0 = b0 + wm * 32 + mt * 16 + (lane >> 2);
        int row1 = row0 + 8;
        float yy0 = g_yy[row0], yy1 = g_yy[row1];
#pragma unroll
        for (int nt = 0; nt < 4; nt++) {
            int col = n0 + wn * 32 + nt * 8 + (lane & 3) * 2;
            float mm0 = g_mm[col], mm1 = g_mm[col + 1];
            float2 v0, v1;
            v0.x = __fsub_rn(__fadd_rn(yy0, mm0), __fmul_rn(2.0f, acc[mt][nt][0]));
            v0.y = __fsub_rn(__fadd_rn(yy0, mm1), __fmul_rn(2.0f, acc[mt][nt][1]));
            v1.x = __fsub_rn(__fadd_rn(yy1, mm0), __fmul_rn(2.0f, acc[mt][nt][2]));
            v1.y = __fsub_rn(__fadd_rn(yy1, mm1), __fmul_rn(2.0f, acc[mt][nt][3]));
            *(float2*)(g_d2 + (size_t)row0 * NN + col) = v0;
            *(float2*)(g_d2 + (size_t)row1 * NN + col) = v1;
        }
    }
}

// ---------------- K3: argmin per row (first-min tie break) ------------------
__global__ __launch_bounds__(128) void k_argmin(float* __restrict__ out_assign) {
    int b = blockIdx.x;
    const float* row = g_d2 + (size_t)b * NN;
    float best = 3.4e38f;
    int   bi = 0;
    for (int n = threadIdx.x; n < NN; n += 128) {
        float v = row[n];
        if (v < best) { best = v; bi = n; }
    }
    __shared__ float sv[128];
    __shared__ int   si[128];
    sv[threadIdx.x] = best;
    si[threadIdx.x] = bi;
    __syncthreads();
    for (int st = 64; st > 0; st >>= 1) {
        if (threadIdx.x < st) {
            float v2 = sv[threadIdx.x + st];
            int   i2 = si[threadIdx.x + st];
            if (v2 < sv[threadIdx.x] ||
                (v2 == sv[threadIdx.x] && i2 < si[threadIdx.x])) {
                sv[threadIdx.x] = v2;
                si[threadIdx.x] = i2;
            }
        }
        __syncthreads();
    }
    if (threadIdx.x == 0) {
        g_assign[b]   = si[0];
        out_assign[b] = (float)si[0];
    }
}

// ---------------- K4: stable per-centroid compaction (1 warp / centroid) ----
__global__ __launch_bounds__(32) void k_group(const float* __restrict__ p_in,
                                              float* __restrict__ p_out) {
    int z = blockIdx.x;
    int lane = threadIdx.x;
    int pos = 0;
    for (int c = 0; c < BB; c += 32) {
        int a = g_assign[c + lane];
        unsigned msk = __ballot_sync(0xffffffffu, a == z);
        if (a == z)
            g_items2[(size_t)z * BB + pos + __popc(msk & ((1u << lane) - 1))] = c + lane;
        pos += __popc(msk);
    }
    if (lane == 0) {
        g_cnt[z] = pos;
        p_out[z] = p_in[z] + (float)pos;
    }
}

// ---------------- K5: per-centroid sequential EMA chains --------------------
__global__ __launch_bounds__(256) void k_update(const float* __restrict__ Y,
                                                const float* __restrict__ Min,
                                                const float* __restrict__ SDin,
                                                float* __restrict__ out_m,
                                                float* __restrict__ out_sd) {
    int z   = blockIdx.x;
    int tid = threadIdx.x;
    float4 mv[8], sv[8];
    const float4* mrow = (const float4*)(Min  + (size_t)z * KD);
    const float4* srow = (const float4*)(SDin + (size_t)z * KD);
#pragma unroll
    for (int t = 0; t < 8; t++) {
        mv[t] = mrow[tid + t * 256];
        sv[t] = srow[tid + t * 256];
    }
    int cnt = g_cnt[z];
    const int* items = g_items2 + (size_t)z * BB;
    for (int j = 0; j < cnt; j++) {
        int i = items[j];
        const float4* yrow = (const float4*)(Y + (size_t)i * KD);
#pragma unroll
        for (int t = 0; t < 8; t++) {
            float4 yv = yrow[tid + t * 256];
            float d;
            mv[t].x = mv[t].x * 0.001f + yv.x * 0.999f;
            d = mv[t].x - yv.x; sv[t].x = d * d * 0.001f + sv[t].x * 0.999f;
            mv[t].y = mv[t].y * 0.001f + yv.y * 0.999f;
            d = mv[t].y - yv.y; sv[t].y = d * d * 0.001f + sv[t].y * 0.999f;
            mv[t].z = mv[t].z * 0.001f + yv.z * 0.999f;
            d = mv[t].z - yv.z; sv[t].z = d * d * 0.001f + sv[t].z * 0.999f;
            mv[t].w = mv[t].w * 0.001f + yv.w * 0.999f;
            d = mv[t].w - yv.w; sv[t].w = d * d * 0.001f + sv[t].w * 0.999f;
        }
    }
    float4* mo = (float4*)(out_m  + (size_t)z * KD);
    float4* so = (float4*)(out_sd + (size_t)z * KD);
#pragma unroll
    for (int t = 0; t < 8; t++) {
        mo[tid + t * 256] = mv[t];
        so[tid + t * 256] = sv[t];
    }
}

// ---------------- launch ----------------------------------------------------
extern "C" void kernel_launch(void* const* d_in, const int* in_sizes, int n_in,
                              void* d_out, int out_size) {
    const float* y  = (const float*)d_in[0];
    const float* m  = (const float*)d_in[1];
    const float* sd = (const float*)d_in[2];
    const float* p  = (const float*)d_in[3];

    float* out      = (float*)d_out;
    float* out_m    = out;
    float* out_sd   = out + (size_t)NN * KD;
    float* out_p    = out + 2 * (size_t)NN * KD;
    float* out_asgn = out_p + NN;

    cudaFuncSetAttribute(k_gemm, cudaFuncAttributeMaxDynamicSharedMemorySize, SM_TOTAL);

    const int conv_blocks = (int)(((size_t)BB * KD + (size_t)NN * KD) / 8 / 256);
    k_convert<<<conv_blocks, 256>>>(y, m);
    k_sumsq<<<BB + NN, 256>>>(y, m);
    dim3 grid(NN / 64, BB / 128);
    k_gemm<<<grid, 256, SM_TOTAL>>>();
    k_argmin<<<BB, 128>>>(out_asgn);
    k_group<<<NN, 32>>>(p, out_p);
    k_update<<<NN, 256>>>(y, m, sd, out_m, out_sd);
}

// round 5
// speedup vs baseline: 1.8850x; 1.0898x over previous
#include <cuda_runtime.h>
#include <cuda_fp16.h>
#include <cstdint>

#define BB 2048   // batch
#define NN 512    // codebook
#define KD 8192   // C*T
#define NC_MAX 16
#define CAND_T 2.0f

// ---------------- device scratch (no allocations allowed) -------------------
__device__ __half g_yh[(size_t)BB * KD];   // fp16 y
__device__ __half g_mh[(size_t)NN * KD];   // fp16 m
__device__ float g_d2[(size_t)BB * NN];    // approx d2' = mm - 2*dot
__device__ float g_mm[NN];
__device__ int   g_assign[BB];
__device__ int   g_cnt[NN];
__device__ int   g_items2[(size_t)NN * BB];
__device__ int   g_nwork;
__device__ int   g_work[BB];
__device__ int   g_ncand[BB];              // 0 => all 512
__device__ int   g_cand[BB][NC_MAX];

// ---------------- PTX helpers (sm_80-level ISA only) ------------------------
__device__ __forceinline__ uint32_t smem_u32(const void* p) {
    uint32_t a;
    asm("{ .reg .u64 t; cvta.to.shared.u64 t, %1; cvt.u32.u64 %0, t; }" : "=r"(a) : "l"(p));
    return a;
}
__device__ __forceinline__ void cp_async16(uint32_t dst, const void* src) {
    asm volatile("cp.async.cg.shared.global [%0], [%1], 16;" :: "r"(dst), "l"(src));
}
__device__ __forceinline__ void ldm_x4(uint32_t* r, uint32_t addr) {
    asm volatile("ldmatrix.sync.aligned.m8n8.x4.shared.b16 {%0,%1,%2,%3}, [%4];"
                 : "=r"(r[0]), "=r"(r[1]), "=r"(r[2]), "=r"(r[3]) : "r"(addr));
}
__device__ __forceinline__ void mma_f16(float* d, const uint32_t* a, const uint32_t* b) {
    asm volatile(
        "mma.sync.aligned.m16n8k16.row.col.f32.f16.f16.f32 "
        "{%0,%1,%2,%3}, {%4,%5,%6,%7}, {%8,%9}, {%0,%1,%2,%3};"
        : "+f"(d[0]), "+f"(d[1]), "+f"(d[2]), "+f"(d[3])
        : "r"(a[0]), "r"(a[1]), "r"(a[2]), "r"(a[3]), "r"(b[0]), "r"(b[1]));
}

// ---------------- K0: fp32 -> fp16 ------------------------------------------
__global__ __launch_bounds__(256) void k_convert(const float* __restrict__ y,
                                                 const float* __restrict__ m) {
    if (blockIdx.x == 0 && threadIdx.x == 0) g_nwork = 0;
    const size_t YC = (size_t)BB * KD / 8;
    size_t gid = (size_t)blockIdx.x * 256 + threadIdx.x;
    const float* src;
    __half* dst;
    size_t e;
    if (gid < YC) { src = y; dst = g_yh; e = gid * 8; }
    else          { src = m; dst = g_mh; e = (gid - YC) * 8; }
    float4 v0 = *(const float4*)(src + e);
    float4 v1 = *(const float4*)(src + e + 4);
    float f[8] = {v0.x, v0.y, v0.z, v0.w, v1.x, v1.y, v1.z, v1.w};
    __half h[8];
#pragma unroll
    for (int i = 0; i < 8; i++) h[i] = __float2half_rn(f[i]);
    *(uint4*)(dst + e) = *(uint4*)h;
}

// ---------------- K1: sum-of-squares for m rows only ------------------------
__global__ __launch_bounds__(256) void k_sumsq(const float* __restrict__ m) {
    int r = blockIdx.x;
    const float4* row4 = (const float4*)(m + (size_t)r * KD);
    float s = 0.f;
    for (int i = threadIdx.x; i < KD / 4; i += 256) {
        float4 v = row4[i];
        s += v.x * v.x + v.y * v.y + v.z * v.z + v.w * v.w;
    }
    __shared__ float sh[256];
    sh[threadIdx.x] = s;
    __syncthreads();
    for (int st = 128; st > 0; st >>= 1) {
        if (threadIdx.x < st) sh[threadIdx.x] += sh[threadIdx.x + st];
        __syncthreads();
    }
    if (threadIdx.x == 0) g_mm[r] = sh[0];
}

// ---------------- K2: fp16 HMMA distance GEMM (single pass) -----------------
// BM=128, BN=64, BK=32, 256 threads = 8 warps (4M x 2N), warp tile 32x32.
#define SROW 80
#define A_MAT 10240        // 128*80
#define B_MAT 5120         // 64*80
#define STG   15360
#define SM_TOTAL (2 * STG)
#define NSTAGES (KD / 32)  // 256

__device__ __forceinline__ void load_stage(uint32_t sb, int buf, int b0, int n0, int k0,
                                           int tid) {
    uint32_t stA = sb + buf * STG;
    uint32_t stB = stA + A_MAT;
#pragma unroll
    for (int t = 0; t < 2; t++) {                 // A: 128 rows x 4 x 16B
        int idx = t * 256 + tid;
        int row = idx >> 2, ch = idx & 3;
        const void* src = g_yh + (size_t)(b0 + row) * KD + k0 + ch * 8;
        cp_async16(stA + row * SROW + ch * 16, src);
    }
    {                                             // B: 64 rows x 4 x 16B
        int row = tid >> 2, ch = tid & 3;
        const void* src = g_mh + (size_t)(n0 + row) * KD + k0 + ch * 8;
        cp_async16(stB + row * SROW + ch * 16, src);
    }
    asm volatile("cp.async.commit_group;");
}

__global__ __launch_bounds__(256, 1) void k_gemm() {
    extern __shared__ char smem[];
    const uint32_t sb = smem_u32(smem);
    const int tid = threadIdx.x;
    const int lane = tid & 31;
    const int wid = tid >> 5;
    const int wm = wid >> 1;          // 0..3 -> M offset wm*32
    const int wn = wid & 1;           // 0..1 -> N offset wn*32
    const int b0 = blockIdx.y * 128;
    const int n0 = blockIdx.x * 64;

    float acc[2][4][4];
#pragma unroll
    for (int i = 0; i < 2; i++)
#pragma unroll
        for (int j = 0; j < 4; j++)
#pragma unroll
            for (int c = 0; c < 4; c++) acc[i][j][c] = 0.f;

    load_stage(sb, 0, b0, n0, 0, tid);

    for (int s = 0; s < NSTAGES; s++) {
        if (s + 1 < NSTAGES) {
            load_stage(sb, (s + 1) & 1, b0, n0, (s + 1) * 32, tid);
            asm volatile("cp.async.wait_group 1;" ::: "memory");
        } else {
            asm volatile("cp.async.wait_group 0;" ::: "memory");
        }
        __syncthreads();

        uint32_t stA = sb + (s & 1) * STG;
        uint32_t stB = stA + A_MAT;

#pragma unroll
        for (int kstep = 0; kstep < 2; kstep++) {
            uint32_t ah[2][4];
#pragma unroll
            for (int mt = 0; mt < 2; mt++) {
                int row = wm * 32 + mt * 16 + (lane & 15);
                int ch = kstep * 2 + (lane >> 4);
                ldm_x4(ah[mt], stA + row * SROW + ch * 16);
            }
            uint32_t bh[4][2];
#pragma unroll
            for (int p = 0; p < 2; p++) {
                int row = wn * 32 + p * 16 + (lane & 7) + (lane >> 4) * 8;
                int ch = kstep * 2 + ((lane >> 3) & 1);
                uint32_t r4[4];
                ldm_x4(r4, stB + row * SROW + ch * 16);
                bh[p * 2 + 0][0] = r4[0]; bh[p * 2 + 0][1] = r4[1];
                bh[p * 2 + 1][0] = r4[2]; bh[p * 2 + 1][1] = r4[3];
            }
#pragma unroll
            for (int mt = 0; mt < 2; mt++)
#pragma unroll
                for (int nt = 0; nt < 4; nt++)
                    mma_f16(acc[mt][nt], ah[mt], bh[nt]);
        }
        __syncthreads();
    }

    // epilogue: approximate d2' = mm - 2*dot   (yy is row-constant; dropped)
#pragma unroll
    for (int mt = 0; mt < 2; mt++) {
        int row0 = b0 + wm * 32 + mt * 16 + (lane >> 2);
        int row1 = row0 + 8;
#pragma unroll
        for (int nt = 0; nt < 4; nt++) {
            int col = n0 + wn * 32 + nt * 8 + (lane & 3) * 2;
            float mm0 = g_mm[col], mm1 = g_mm[col + 1];
            float2 v0, v1;
            v0.x = mm0 - 2.0f * acc[mt][nt][0];
            v0.y = mm1 - 2.0f * acc[mt][nt][1];
            v1.x = mm0 - 2.0f * acc[mt][nt][2];
            v1.y = mm1 - 2.0f * acc[mt][nt][3];
            *(float2*)(g_d2 + (size_t)row0 * NN + col) = v0;
            *(float2*)(g_d2 + (size_t)row1 * NN + col) = v1;
        }
    }
}

// ---------------- K3: argmin + near-tie candidate collection ----------------
__global__ __launch_bounds__(128) void k_argmin_cand(float* __restrict__ out_assign) {
    int b = blockIdx.x;
    int tid = threadIdx.x;
    __shared__ float srow[NN];
    const float4* row4 = (const float4*)(g_d2 + (size_t)b * NN);
    for (int i = tid; i < NN / 4; i += 128) *(float4*)&srow[i * 4] = row4[i];
    __syncthreads();

    float best = 3.4e38f;
    int   bi = 0;
    for (int n = tid; n < NN; n += 128) {
        float v = srow[n];
        if (v < best) { best = v; bi = n; }
    }
    __shared__ float sv[128];
    __shared__ int   si[128];
    sv[tid] = best;
    si[tid] = bi;
    __syncthreads();
    for (int st = 64; st > 0; st >>= 1) {
        if (tid < st) {
            float v2 = sv[tid + st];
            int   i2 = si[tid + st];
            if (v2 < sv[tid] || (v2 == sv[tid] && i2 < si[tid])) {
                sv[tid] = v2;
                si[tid] = i2;
            }
        }
        __syncthreads();
    }
    __shared__ int scnt;
    __shared__ int scand[NC_MAX];
    if (tid == 0) scnt = 0;
    __syncthreads();
    float thr = sv[0] + CAND_T;
    for (int n = tid; n < NN; n += 128) {
        if (srow[n] <= thr) {
            int pos = atomicAdd(&scnt, 1);
            if (pos < NC_MAX) scand[pos] = n;
        }
    }
    __syncthreads();
    if (tid == 0) {
        int minidx = si[0];
        g_assign[b]   = minidx;            // provisional (final if single cand)
        out_assign[b] = (float)minidx;
        if (scnt > 1) {
            int wi = atomicAdd(&g_nwork, 1);
            g_work[wi] = b;
            if (scnt <= NC_MAX) {
                g_ncand[b] = scnt;
                for (int c = 0; c < scnt; c++) g_cand[b][c] = scand[c];
            } else {
                g_ncand[b] = 0;            // sentinel: rescore all 512
            }
        }
    }
}

// ---------------- K3b: exact f64 rescore of flagged rows --------------------
__global__ __launch_bounds__(128) void k_rescore(const float* __restrict__ y,
                                                 const float* __restrict__ m,
                                                 float* __restrict__ out_assign) {
    int w = blockIdx.x;
    if (w >= g_nwork) return;
    int b  = g_work[w];
    int nc = g_ncand[b];
    int total = (nc == 0) ? NN : nc;
    int tid = threadIdx.x;
    const float* yrow = y + (size_t)b * KD;
    __shared__ double sred[128];
    __shared__ double sbestv;
    __shared__ int    sbesti;
    if (tid == 0) { sbestv = 1e300; sbesti = 0x7fffffff; }
    __syncthreads();
    for (int c = 0; c < total; c++) {
        int n = (nc == 0) ? c : g_cand[b][c];
        const float* mrow = m + (size_t)n * KD;
        double s = 0.0;
        for (int k = tid; k < KD; k += 128) {
            double mk = (double)mrow[k];
            s += mk * (mk - 2.0 * (double)yrow[k]);
        }
        sred[tid] = s;
        __syncthreads();
        for (int st = 64; st > 0; st >>= 1) {
            if (tid < st) sred[tid] += sred[tid + st];
            __syncthreads();
        }
        if (tid == 0) {
            double v = sred[0];
            if (v < sbestv || (v == sbestv && n < sbesti)) { sbestv = v; sbesti = n; }
        }
        __syncthreads();
    }
    if (tid == 0) {
        g_assign[b]   = sbesti;
        out_assign[b] = (float)sbesti;
    }
}

// ---------------- K4: stable per-centroid compaction (1 warp / centroid) ----
__global__ __launch_bounds__(32) void k_group(const float* __restrict__ p_in,
                                              float* __restrict__ p_out) {
    int z = blockIdx.x;
    int lane = threadIdx.x;
    int pos = 0;
    for (int c = 0; c < BB; c += 32) {
        int a = g_assign[c + lane];
        unsigned msk = __ballot_sync(0xffffffffu, a == z);
        if (a == z)
            g_items2[(size_t)z * BB + pos + __popc(msk & ((1u << lane) - 1))] = c + lane;
        pos += __popc(msk);
    }
    if (lane == 0) {
        g_cnt[z] = pos;
        p_out[z] = p_in[z] + (float)pos;
    }
}

// ---------------- K5: per-centroid sequential EMA chains --------------------
__global__ __launch_bounds__(256) void k_update(const float* __restrict__ Y,
                                                const float* __restrict__ Min,
                                                const float* __restrict__ SDin,
                                                float* __restrict__ out_m,
                                                float* __restrict__ out_sd) {
    int z   = blockIdx.x;
    int tid = threadIdx.x;
    float4 mv[8], sv[8];
    const float4* mrow = (const float4*)(Min  + (size_t)z * KD);
    const float4* srow = (const float4*)(SDin + (size_t)z * KD);
#pragma unroll
    for (int t = 0; t < 8; t++) {
        mv[t] = mrow[tid + t * 256];
        sv[t] = srow[tid + t * 256];
    }
    int cnt = g_cnt[z];
    const int* items = g_items2 + (size_t)z * BB;
    for (int j = 0; j < cnt; j++) {
        int i = items[j];
        const float4* yrow = (const float4*)(Y + (size_t)i * KD);
#pragma unroll
        for (int t = 0; t < 8; t++) {
            float4 yv = yrow[tid + t * 256];
            float d;
            mv[t].x = mv[t].x * 0.001f + yv.x * 0.999f;
            d = mv[t].x - yv.x; sv[t].x = d * d * 0.001f + sv[t].x * 0.999f;
            mv[t].y = mv[t].y * 0.001f + yv.y * 0.999f;
            d = mv[t].y - yv.y; sv[t].y = d * d * 0.001f + sv[t].y * 0.999f;
            mv[t].z = mv[t].z * 0.001f + yv.z * 0.999f;
            d = mv[t].z - yv.z; sv[t].z = d * d * 0.001f + sv[t].z * 0.999f;
            mv[t].w = mv[t].w * 0.001f + yv.w * 0.999f;
            d = mv[t].w - yv.w; sv[t].w = d * d * 0.001f + sv[t].w * 0.999f;
        }
    }
    float4* mo = (float4*)(out_m  + (size_t)z * KD);
    float4* so = (float4*)(out_sd + (size_t)z * KD);
#pragma unroll
    for (int t = 0; t < 8; t++) {
        mo[tid + t * 256] = mv[t];
        so[tid + t * 256] = sv[t];
    }
}

// ---------------- launch ----------------------------------------------------
extern "C" void kernel_launch(void* const* d_in, const int* in_sizes, int n_in,
                              void* d_out, int out_size) {
    const float* y  = (const float*)d_in[0];
    const float* m  = (const float*)d_in[1];
    const float* sd = (const float*)d_in[2];
    const float* p  = (const float*)d_in[3];

    float* out      = (float*)d_out;
    float* out_m    = out;
    float* out_sd   = out + (size_t)NN * KD;
    float* out_p    = out + 2 * (size_t)NN * KD;
    float* out_asgn = out_p + NN;

    cudaFuncSetAttribute(k_gemm, cudaFuncAttributeMaxDynamicSharedMemorySize, SM_TOTAL);

    const int conv_blocks = (int)(((size_t)BB * KD + (size_t)NN * KD) / 8 / 256);
    k_convert<<<conv_blocks, 256>>>(y, m);
    k_sumsq<<<NN, 256>>>(m);
    dim3 grid(NN / 64, BB / 128);
    k_gemm<<<grid, 256, SM_TOTAL>>>();
    k_argmin_cand<<<BB, 128>>>(out_asgn);
    k_rescore<<<BB, 128>>>(y, m, out_asgn);
    k_group<<<NN, 32>>>(p, out_p);
    k_update<<<NN, 256>>>(y, m, sd, out_m, out_sd);
}

// round 6
// speedup vs baseline: 2.0999x; 1.1140x over previous
#include <cuda_runtime.h>
#include <cuda_fp16.h>
#include <cstdint>

#define BB 2048   // batch
#define NN 512    // codebook
#define KD 8192   // C*T
#define NC_MAX 16
#define CAND_T 2.0f

// ---------------- device scratch (no allocations allowed) -------------------
__device__ __half g_yh[(size_t)BB * KD];   // fp16 y
__device__ __half g_mh[(size_t)NN * KD];   // fp16 m
__device__ float g_d2[(size_t)BB * NN];    // approx d2' = mm - 2*dot
__device__ float g_mm[NN];
__device__ int   g_assign[BB];
__device__ int   g_cnt[NN];
__device__ int   g_items2[(size_t)NN * BB];
__device__ int   g_nwork;
__device__ int   g_work[BB];
__device__ int   g_ncand[BB];              // 0 => all 512
__device__ int   g_cand[BB][NC_MAX];

// ---------------- PTX helpers (sm_80-level ISA only) ------------------------
__device__ __forceinline__ uint32_t smem_u32(const void* p) {
    uint32_t a;
    asm("{ .reg .u64 t; cvta.to.shared.u64 t, %1; cvt.u32.u64 %0, t; }" : "=r"(a) : "l"(p));
    return a;
}
__device__ __forceinline__ void cp_async16(uint32_t dst, const void* src) {
    asm volatile("cp.async.cg.shared.global [%0], [%1], 16;" :: "r"(dst), "l"(src));
}
__device__ __forceinline__ void ldm_x4(uint32_t* r, uint32_t addr) {
    asm volatile("ldmatrix.sync.aligned.m8n8.x4.shared.b16 {%0,%1,%2,%3}, [%4];"
                 : "=r"(r[0]), "=r"(r[1]), "=r"(r[2]), "=r"(r[3]) : "r"(addr));
}
__device__ __forceinline__ void mma_f16(float* d, const uint32_t* a, const uint32_t* b) {
    asm volatile(
        "mma.sync.aligned.m16n8k16.row.col.f32.f16.f16.f32 "
        "{%0,%1,%2,%3}, {%4,%5,%6,%7}, {%8,%9}, {%0,%1,%2,%3};"
        : "+f"(d[0]), "+f"(d[1]), "+f"(d[2]), "+f"(d[3])
        : "r"(a[0]), "r"(a[1]), "r"(a[2]), "r"(a[3]), "r"(b[0]), "r"(b[1]));
}

// ---------------- K0: fp32 -> fp16 ------------------------------------------
__global__ __launch_bounds__(256) void k_convert(const float* __restrict__ y,
                                                 const float* __restrict__ m) {
    if (blockIdx.x == 0 && threadIdx.x == 0) g_nwork = 0;
    const size_t YC = (size_t)BB * KD / 8;
    size_t gid = (size_t)blockIdx.x * 256 + threadIdx.x;
    const float* src;
    __half* dst;
    size_t e;
    if (gid < YC) { src = y; dst = g_yh; e = gid * 8; }
    else          { src = m; dst = g_mh; e = (gid - YC) * 8; }
    float4 v0 = *(const float4*)(src + e);
    float4 v1 = *(const float4*)(src + e + 4);
    float f[8] = {v0.x, v0.y, v0.z, v0.w, v1.x, v1.y, v1.z, v1.w};
    __half h[8];
#pragma unroll
    for (int i = 0; i < 8; i++) h[i] = __float2half_rn(f[i]);
    *(uint4*)(dst + e) = *(uint4*)h;
}

// ---------------- K1: sum-of-squares for m rows only ------------------------
__global__ __launch_bounds__(256) void k_sumsq(const float* __restrict__ m) {
    int r = blockIdx.x;
    const float4* row4 = (const float4*)(m + (size_t)r * KD);
    float s = 0.f;
    for (int i = threadIdx.x; i < KD / 4; i += 256) {
        float4 v = row4[i];
        s += v.x * v.x + v.y * v.y + v.z * v.z + v.w * v.w;
    }
    __shared__ float sh[256];
    sh[threadIdx.x] = s;
    __syncthreads();
    for (int st = 128; st > 0; st >>= 1) {
        if (threadIdx.x < st) sh[threadIdx.x] += sh[threadIdx.x + st];
        __syncthreads();
    }
    if (threadIdx.x == 0) g_mm[r] = sh[0];
}

// ---------------- K2: fp16 HMMA distance GEMM, 4-deep pipeline --------------
// BM=128, BN=64, BK=64, 256 threads = 8 warps (4M x 2N), warp tile 32x32.
// smem rows padded to 144B -> conflict-free ldmatrix.
#define SROW 144
#define A_MAT (128 * SROW)       // 18432
#define B_MAT (64 * SROW)        // 9216
#define STG   (A_MAT + B_MAT)    // 27648
#define DEPTH 4
#define SM_TOTAL (DEPTH * STG)   // 110592
#define NSTAGES (KD / 64)        // 128

__device__ __forceinline__ void load_stage(uint32_t sb, int buf, int b0, int n0, int k0,
                                           int tid) {
    uint32_t stA = sb + buf * STG;
    uint32_t stB = stA + A_MAT;
#pragma unroll
    for (int t = 0; t < 4; t++) {                 // A: 128 rows x 8 x 16B
        int idx = t * 256 + tid;
        int row = idx >> 3, ch = idx & 7;
        const void* src = g_yh + (size_t)(b0 + row) * KD + k0 + ch * 8;
        cp_async16(stA + row * SROW + ch * 16, src);
    }
#pragma unroll
    for (int t = 0; t < 2; t++) {                 // B: 64 rows x 8 x 16B
        int idx = t * 256 + tid;
        int row = idx >> 3, ch = idx & 7;
        const void* src = g_mh + (size_t)(n0 + row) * KD + k0 + ch * 8;
        cp_async16(stB + row * SROW + ch * 16, src);
    }
    asm volatile("cp.async.commit_group;");
}

__global__ __launch_bounds__(256, 1) void k_gemm() {
    extern __shared__ char smem[];
    const uint32_t sb = smem_u32(smem);
    const int tid = threadIdx.x;
    const int lane = tid & 31;
    const int wid = tid >> 5;
    const int wm = wid >> 1;          // 0..3 -> M offset wm*32
    const int wn = wid & 1;           // 0..1 -> N offset wn*32
    const int b0 = blockIdx.y * 128;
    const int n0 = blockIdx.x * 64;

    float acc[2][4][4];
#pragma unroll
    for (int i = 0; i < 2; i++)
#pragma unroll
        for (int j = 0; j < 4; j++)
#pragma unroll
            for (int c = 0; c < 4; c++) acc[i][j][c] = 0.f;

    load_stage(sb, 0, b0, n0, 0, tid);
    load_stage(sb, 1, b0, n0, 64, tid);
    load_stage(sb, 2, b0, n0, 128, tid);

    for (int s = 0; s < NSTAGES; s++) {
        if (s < NSTAGES - 2)      asm volatile("cp.async.wait_group 2;" ::: "memory");
        else if (s == NSTAGES - 2) asm volatile("cp.async.wait_group 1;" ::: "memory");
        else                       asm volatile("cp.async.wait_group 0;" ::: "memory");
        __syncthreads();

        if (s + 3 < NSTAGES)
            load_stage(sb, (s + 3) & 3, b0, n0, (s + 3) * 64, tid);

        uint32_t stA = sb + (s & 3) * STG;
        uint32_t stB = stA + A_MAT;

#pragma unroll
        for (int kstep = 0; kstep < 4; kstep++) {
            uint32_t ah[2][4];
#pragma unroll
            for (int mt = 0; mt < 2; mt++) {
                int row = wm * 32 + mt * 16 + (lane & 15);
                int ch = kstep * 2 + (lane >> 4);
                ldm_x4(ah[mt], stA + row * SROW + ch * 16);
            }
            uint32_t bh[4][2];
#pragma unroll
            for (int p = 0; p < 2; p++) {
                int row = wn * 32 + p * 16 + (lane & 7) + (lane >> 4) * 8;
                int ch = kstep * 2 + ((lane >> 3) & 1);
                uint32_t r4[4];
                ldm_x4(r4, stB + row * SROW + ch * 16);
                bh[p * 2 + 0][0] = r4[0]; bh[p * 2 + 0][1] = r4[1];
                bh[p * 2 + 1][0] = r4[2]; bh[p * 2 + 1][1] = r4[3];
            }
#pragma unroll
            for (int mt = 0; mt < 2; mt++)
#pragma unroll
                for (int nt = 0; nt < 4; nt++)
                    mma_f16(acc[mt][nt], ah[mt], bh[nt]);
        }
    }

    // epilogue: approximate d2' = mm - 2*dot   (yy is row-constant; dropped)
#pragma unroll
    for (int mt = 0; mt < 2; mt++) {
        int row0 = b0 + wm * 32 + mt * 16 + (lane >> 2);
        int row1 = row0 + 8;
#pragma unroll
        for (int nt = 0; nt < 4; nt++) {
            int col = n0 + wn * 32 + nt * 8 + (lane & 3) * 2;
            float mm0 = g_mm[col], mm1 = g_mm[col + 1];
            float2 v0, v1;
            v0.x = mm0 - 2.0f * acc[mt][nt][0];
            v0.y = mm1 - 2.0f * acc[mt][nt][1];
            v1.x = mm0 - 2.0f * acc[mt][nt][2];
            v1.y = mm1 - 2.0f * acc[mt][nt][3];
            *(float2*)(g_d2 + (size_t)row0 * NN + col) = v0;
            *(float2*)(g_d2 + (size_t)row1 * NN + col) = v1;
        }
    }
}

// ---------------- K3: argmin + near-tie candidate collection ----------------
__global__ __launch_bounds__(128) void k_argmin_cand(float* __restrict__ out_assign) {
    int b = blockIdx.x;
    int tid = threadIdx.x;
    __shared__ float srow[NN];
    const float4* row4 = (const float4*)(g_d2 + (size_t)b * NN);
    for (int i = tid; i < NN / 4; i += 128) *(float4*)&srow[i * 4] = row4[i];
    __syncthreads();

    float best = 3.4e38f;
    int   bi = 0;
    for (int n = tid; n < NN; n += 128) {
        float v = srow[n];
        if (v < best) { best = v; bi = n; }
    }
    __shared__ float sv[128];
    __shared__ int   si[128];
    sv[tid] = best;
    si[tid] = bi;
    __syncthreads();
    for (int st = 64; st > 0; st >>= 1) {
        if (tid < st) {
            float v2 = sv[tid + st];
            int   i2 = si[tid + st];
            if (v2 < sv[tid] || (v2 == sv[tid] && i2 < si[tid])) {
                sv[tid] = v2;
                si[tid] = i2;
            }
        }
        __syncthreads();
    }
    __shared__ int scnt;
    __shared__ int scand[NC_MAX];
    if (tid == 0) scnt = 0;
    __syncthreads();
    float thr = sv[0] + CAND_T;
    for (int n = tid; n < NN; n += 128) {
        if (srow[n] <= thr) {
            int pos = atomicAdd(&scnt, 1);
            if (pos < NC_MAX) scand[pos] = n;
        }
    }
    __syncthreads();
    if (tid == 0) {
        int minidx = si[0];
        g_assign[b]   = minidx;            // provisional (final if single cand)
        out_assign[b] = (float)minidx;
        if (scnt > 1) {
            int wi = atomicAdd(&g_nwork, 1);
            g_work[wi] = b;
            if (scnt <= NC_MAX) {
                g_ncand[b] = scnt;
                for (int c = 0; c < scnt; c++) g_cand[b][c] = scand[c];
            } else {
                g_ncand[b] = 0;            // sentinel: rescore all 512
            }
        }
    }
}

// ---------------- K3b: exact f64 rescore of flagged rows --------------------
__global__ __launch_bounds__(128) void k_rescore(const float* __restrict__ y,
                                                 const float* __restrict__ m,
                                                 float* __restrict__ out_assign) {
    int w = blockIdx.x;
    if (w >= g_nwork) return;
    int b  = g_work[w];
    int nc = g_ncand[b];
    int total = (nc == 0) ? NN : nc;
    int tid = threadIdx.x;
    const float* yrow = y + (size_t)b * KD;
    __shared__ double sred[128];
    __shared__ double sbestv;
    __shared__ int    sbesti;
    if (tid == 0) { sbestv = 1e300; sbesti = 0x7fffffff; }
    __syncthreads();
    for (int c = 0; c < total; c++) {
        int n = (nc == 0) ? c : g_cand[b][c];
        const float* mrow = m + (size_t)n * KD;
        double s = 0.0;
        for (int k = tid; k < KD; k += 128) {
            double mk = (double)mrow[k];
            s += mk * (mk - 2.0 * (double)yrow[k]);
        }
        sred[tid] = s;
        __syncthreads();
        for (int st = 64; st > 0; st >>= 1) {
            if (tid < st) sred[tid] += sred[tid + st];
            __syncthreads();
        }
        if (tid == 0) {
            double v = sred[0];
            if (v < sbestv || (v == sbestv && n < sbesti)) { sbestv = v; sbesti = n; }
        }
        __syncthreads();
    }
    if (tid == 0) {
        g_assign[b]   = sbesti;
        out_assign[b] = (float)sbesti;
    }
}

// ---------------- K4: stable per-centroid compaction (1 warp / centroid) ----
__global__ __launch_bounds__(32) void k_group(const float* __restrict__ p_in,
                                              float* __restrict__ p_out) {
    int z = blockIdx.x;
    int lane = threadIdx.x;
    int pos = 0;
    for (int c = 0; c < BB; c += 32) {
        int a = g_assign[c + lane];
        unsigned msk = __ballot_sync(0xffffffffu, a == z);
        if (a == z)
            g_items2[(size_t)z * BB + pos + __popc(msk & ((1u << lane) - 1))] = c + lane;
        pos += __popc(msk);
    }
    if (lane == 0) {
        g_cnt[z] = pos;
        p_out[z] = p_in[z] + (float)pos;
    }
}

// ---------------- K5: per-centroid sequential EMA chains --------------------
__global__ __launch_bounds__(256) void k_update(const float* __restrict__ Y,
                                                const float* __restrict__ Min,
                                                const float* __restrict__ SDin,
                                                float* __restrict__ out_m,
                                                float* __restrict__ out_sd) {
    int z   = blockIdx.x;
    int tid = threadIdx.x;
    float4 mv[8], sv[8];
    const float4* mrow = (const float4*)(Min  + (size_t)z * KD);
    const float4* srow = (const float4*)(SDin + (size_t)z * KD);
#pragma unroll
    for (int t = 0; t < 8; t++) {
        mv[t] = mrow[tid + t * 256];
        sv[t] = srow[tid + t * 256];
    }
    int cnt = g_cnt[z];
    const int* items = g_items2 + (size_t)z * BB;
    for (int j = 0; j < cnt; j++) {
        int i = items[j];
        const float4* yrow = (const float4*)(Y + (size_t)i * KD);
#pragma unroll
        for (int t = 0; t < 8; t++) {
            float4 yv = yrow[tid + t * 256];
            float d;
            mv[t].x = mv[t].x * 0.001f + yv.x * 0.999f;
            d = mv[t].x - yv.x; sv[t].x = d * d * 0.001f + sv[t].x * 0.999f;
            mv[t].y = mv[t].y * 0.001f + yv.y * 0.999f;
            d = mv[t].y - yv.y; sv[t].y = d * d * 0.001f + sv[t].y * 0.999f;
            mv[t].z = mv[t].z * 0.001f + yv.z * 0.999f;
            d = mv[t].z - yv.z; sv[t].z = d * d * 0.001f + sv[t].z * 0.999f;
            mv[t].w = mv[t].w * 0.001f + yv.w * 0.999f;
            d = mv[t].w - yv.w; sv[t].w = d * d * 0.001f + sv[t].w * 0.999f;
        }
    }
    float4* mo = (float4*)(out_m  + (size_t)z * KD);
    float4* so = (float4*)(out_sd + (size_t)z * KD);
#pragma unroll
    for (int t = 0; t < 8; t++) {
        mo[tid + t * 256] = mv[t];
        so[tid + t * 256] = sv[t];
    }
}

// ---------------- launch ----------------------------------------------------
extern "C" void kernel_launch(void* const* d_in, const int* in_sizes, int n_in,
                              void* d_out, int out_size) {
    const float* y  = (const float*)d_in[0];
    const float* m  = (const float*)d_in[1];
    const float* sd = (const float*)d_in[2];
    const float* p  = (const float*)d_in[3];

    float* out      = (float*)d_out;
    float* out_m    = out;
    float* out_sd   = out + (size_t)NN * KD;
    float* out_p    = out + 2 * (size_t)NN * KD;
    float* out_asgn = out_p + NN;

    cudaFuncSetAttribute(k_gemm, cudaFuncAttributeMaxDynamicSharedMemorySize, SM_TOTAL);

    const int conv_blocks = (int)(((size_t)BB * KD + (size_t)NN * KD) / 8 / 256);
    k_convert<<<conv_blocks, 256>>>(y, m);
    k_sumsq<<<NN, 256>>>(m);
    dim3 grid(NN / 64, BB / 128);
    k_gemm<<<grid, 256, SM_TOTAL>>>();
    k_argmin_cand<<<BB, 128>>>(out_asgn);
    k_rescore<<<BB, 128>>>(y, m, out_asgn);
    k_group<<<NN, 32>>>(p, out_p);
    k_update<<<NN, 256>>>(y, m, sd, out_m, out_sd);
}

// round 7
// speedup vs baseline: 4.0365x; 1.9223x over previous
#include <cuda_runtime.h>
#include <cuda_fp16.h>
#include <cstdint>

#define BB 2048   // batch
#define NN 512    // codebook
#define KD 8192   // C*T
#define NC_MAX 16
#define CAND_T 2.0f
#define KSPL 2
#define KHALF (KD / KSPL)        // 4096

// ---------------- device scratch (no allocations allowed) -------------------
__device__ __half g_yh[(size_t)BB * KD];   // fp16 y
__device__ __half g_mh[(size_t)NN * KD];   // fp16 m
__device__ float g_part[KSPL][BB][NN];     // partial dots (8 MB)
__device__ float g_mm[NN];
__device__ int   g_assign[BB];
__device__ int   g_cnt[NN];
__device__ int   g_items2[(size_t)NN * BB];
__device__ int   g_nwork;
__device__ int   g_work[BB];
__device__ int   g_ncand[BB];              // 0 => all 512
__device__ int   g_cand[BB][NC_MAX];

// ---------------- PTX helpers (sm_80-level ISA only) ------------------------
__device__ __forceinline__ uint32_t smem_u32(const void* p) {
    uint32_t a;
    asm("{ .reg .u64 t; cvta.to.shared.u64 t, %1; cvt.u32.u64 %0, t; }" : "=r"(a) : "l"(p));
    return a;
}
__device__ __forceinline__ void cp_async16(uint32_t dst, const void* src) {
    asm volatile("cp.async.cg.shared.global [%0], [%1], 16;" :: "r"(dst), "l"(src));
}
__device__ __forceinline__ void ldm_x4(uint32_t* r, uint32_t addr) {
    asm volatile("ldmatrix.sync.aligned.m8n8.x4.shared.b16 {%0,%1,%2,%3}, [%4];"
                 : "=r"(r[0]), "=r"(r[1]), "=r"(r[2]), "=r"(r[3]) : "r"(addr));
}
__device__ __forceinline__ void mma_f16(float* d, const uint32_t* a, const uint32_t* b) {
    asm volatile(
        "mma.sync.aligned.m16n8k16.row.col.f32.f16.f16.f32 "
        "{%0,%1,%2,%3}, {%4,%5,%6,%7}, {%8,%9}, {%0,%1,%2,%3};"
        : "+f"(d[0]), "+f"(d[1]), "+f"(d[2]), "+f"(d[3])
        : "r"(a[0]), "r"(a[1]), "r"(a[2]), "r"(a[3]), "r"(b[0]), "r"(b[1]));
}

// ---------------- K0: fp32 -> fp16 ------------------------------------------
__global__ __launch_bounds__(256) void k_convert(const float* __restrict__ y,
                                                 const float* __restrict__ m) {
    if (blockIdx.x == 0 && threadIdx.x == 0) g_nwork = 0;
    const size_t YC = (size_t)BB * KD / 8;
    size_t gid = (size_t)blockIdx.x * 256 + threadIdx.x;
    const float* src;
    __half* dst;
    size_t e;
    if (gid < YC) { src = y; dst = g_yh; e = gid * 8; }
    else          { src = m; dst = g_mh; e = (gid - YC) * 8; }
    float4 v0 = *(const float4*)(src + e);
    float4 v1 = *(const float4*)(src + e + 4);
    float f[8] = {v0.x, v0.y, v0.z, v0.w, v1.x, v1.y, v1.z, v1.w};
    __half h[8];
#pragma unroll
    for (int i = 0; i < 8; i++) h[i] = __float2half_rn(f[i]);
    *(uint4*)(dst + e) = *(uint4*)h;
}

// ---------------- K1: sum-of-squares for m rows only ------------------------
__global__ __launch_bounds__(256) void k_sumsq(const float* __restrict__ m) {
    int r = blockIdx.x;
    const float4* row4 = (const float4*)(m + (size_t)r * KD);
    float s = 0.f;
    for (int i = threadIdx.x; i < KD / 4; i += 256) {
        float4 v = row4[i];
        s += v.x * v.x + v.y * v.y + v.z * v.z + v.w * v.w;
    }
    __shared__ float sh[256];
    sh[threadIdx.x] = s;
    __syncthreads();
    for (int st = 128; st > 0; st >>= 1) {
        if (threadIdx.x < st) sh[threadIdx.x] += sh[threadIdx.x + st];
        __syncthreads();
    }
    if (threadIdx.x == 0) g_mm[r] = sh[0];
}

// ---------------- K2: fp16 HMMA dot GEMM, K-split 2, 2 CTA/SM ---------------
// BM=128, BN=64, BK=64, 256 threads = 8 warps (4M x 2N), warp tile 32x32.
// smem rows padded to 144B -> conflict-free ldmatrix.
#define SROW 144
#define A_MAT (128 * SROW)       // 18432
#define B_MAT (64 * SROW)        // 9216
#define STG   (A_MAT + B_MAT)    // 27648
#define DEPTH 4
#define SM_TOTAL (DEPTH * STG)   // 110592
#define NSTAGES (KHALF / 64)     // 64

__device__ __forceinline__ void load_stage(uint32_t sb, int buf, int b0, int n0, int k0,
                                           int tid) {
    uint32_t stA = sb + buf * STG;
    uint32_t stB = stA + A_MAT;
#pragma unroll
    for (int t = 0; t < 4; t++) {                 // A: 128 rows x 8 x 16B
        int idx = t * 256 + tid;
        int row = idx >> 3, ch = idx & 7;
        const void* src = g_yh + (size_t)(b0 + row) * KD + k0 + ch * 8;
        cp_async16(stA + row * SROW + ch * 16, src);
    }
#pragma unroll
    for (int t = 0; t < 2; t++) {                 // B: 64 rows x 8 x 16B
        int idx = t * 256 + tid;
        int row = idx >> 3, ch = idx & 7;
        const void* src = g_mh + (size_t)(n0 + row) * KD + k0 + ch * 8;
        cp_async16(stB + row * SROW + ch * 16, src);
    }
    asm volatile("cp.async.commit_group;");
}

__global__ __launch_bounds__(256, 2) void k_gemm() {
    extern __shared__ char smem[];
    const uint32_t sb = smem_u32(smem);
    const int tid = threadIdx.x;
    const int lane = tid & 31;
    const int wid = tid >> 5;
    const int wm = wid >> 1;          // 0..3 -> M offset wm*32
    const int wn = wid & 1;           // 0..1 -> N offset wn*32
    const int b0 = blockIdx.y * 128;
    const int n0 = blockIdx.x * 64;
    const int ks = blockIdx.z;
    const int kbase = ks * KHALF;

    float acc[2][4][4];
#pragma unroll
    for (int i = 0; i < 2; i++)
#pragma unroll
        for (int j = 0; j < 4; j++)
#pragma unroll
            for (int c = 0; c < 4; c++) acc[i][j][c] = 0.f;

    load_stage(sb, 0, b0, n0, kbase, tid);
    load_stage(sb, 1, b0, n0, kbase + 64, tid);
    load_stage(sb, 2, b0, n0, kbase + 128, tid);

    for (int s = 0; s < NSTAGES; s++) {
        if (s < NSTAGES - 2)       asm volatile("cp.async.wait_group 2;" ::: "memory");
        else if (s == NSTAGES - 2) asm volatile("cp.async.wait_group 1;" ::: "memory");
        else                       asm volatile("cp.async.wait_group 0;" ::: "memory");
        __syncthreads();

        if (s + 3 < NSTAGES)
            load_stage(sb, (s + 3) & 3, b0, n0, kbase + (s + 3) * 64, tid);

        uint32_t stA = sb + (s & 3) * STG;
        uint32_t stB = stA + A_MAT;

#pragma unroll
        for (int kstep = 0; kstep < 4; kstep++) {
            uint32_t ah[2][4];
#pragma unroll
            for (int mt = 0; mt < 2; mt++) {
                int row = wm * 32 + mt * 16 + (lane & 15);
                int ch = kstep * 2 + (lane >> 4);
                ldm_x4(ah[mt], stA + row * SROW + ch * 16);
            }
            uint32_t bh[4][2];
#pragma unroll
            for (int p = 0; p < 2; p++) {
                int row = wn * 32 + p * 16 + (lane & 7) + (lane >> 4) * 8;
                int ch = kstep * 2 + ((lane >> 3) & 1);
                uint32_t r4[4];
                ldm_x4(r4, stB + row * SROW + ch * 16);
                bh[p * 2 + 0][0] = r4[0]; bh[p * 2 + 0][1] = r4[1];
                bh[p * 2 + 1][0] = r4[2]; bh[p * 2 + 1][1] = r4[3];
            }
#pragma unroll
            for (int mt = 0; mt < 2; mt++)
#pragma unroll
                for (int nt = 0; nt < 4; nt++)
                    mma_f16(acc[mt][nt], ah[mt], bh[nt]);
        }
    }

    // epilogue: store partial dot for this K half
#pragma unroll
    for (int mt = 0; mt < 2; mt++) {
        int row0 = b0 + wm * 32 + mt * 16 + (lane >> 2);
        int row1 = row0 + 8;
#pragma unroll
        for (int nt = 0; nt < 4; nt++) {
            int col = n0 + wn * 32 + nt * 8 + (lane & 3) * 2;
            float2 v0, v1;
            v0.x = acc[mt][nt][0]; v0.y = acc[mt][nt][1];
            v1.x = acc[mt][nt][2]; v1.y = acc[mt][nt][3];
            *(float2*)(&g_part[ks][row0][col]) = v0;
            *(float2*)(&g_part[ks][row1][col]) = v1;
        }
    }
}

// ---------------- K3: combine partials, argmin + candidate collection -------
__global__ __launch_bounds__(128) void k_argmin_cand(float* __restrict__ out_assign) {
    int b = blockIdx.x;
    int tid = threadIdx.x;
    __shared__ float srow[NN];
    const float4* p0 = (const float4*)&g_part[0][b][0];
    const float4* p1 = (const float4*)&g_part[1][b][0];
    const float4* mm4 = (const float4*)g_mm;
    for (int i = tid; i < NN / 4; i += 128) {
        float4 a = p0[i], c = p1[i], mm = mm4[i];
        float4 r;
        r.x = mm.x - 2.0f * (a.x + c.x);
        r.y = mm.y - 2.0f * (a.y + c.y);
        r.z = mm.z - 2.0f * (a.z + c.z);
        r.w = mm.w - 2.0f * (a.w + c.w);
        *(float4*)&srow[i * 4] = r;
    }
    __syncthreads();

    float best = 3.4e38f;
    int   bi = 0;
    for (int n = tid; n < NN; n += 128) {
        float v = srow[n];
        if (v < best) { best = v; bi = n; }
    }
    __shared__ float sv[128];
    __shared__ int   si[128];
    sv[tid] = best;
    si[tid] = bi;
    __syncthreads();
    for (int st = 64; st > 0; st >>= 1) {
        if (tid < st) {
            float v2 = sv[tid + st];
            int   i2 = si[tid + st];
            if (v2 < sv[tid] || (v2 == sv[tid] && i2 < si[tid])) {
                sv[tid] = v2;
                si[tid] = i2;
            }
        }
        __syncthreads();
    }
    __shared__ int scnt;
    __shared__ int scand[NC_MAX];
    if (tid == 0) scnt = 0;
    __syncthreads();
    float thr = sv[0] + CAND_T;
    for (int n = tid; n < NN; n += 128) {
        if (srow[n] <= thr) {
            int pos = atomicAdd(&scnt, 1);
            if (pos < NC_MAX) scand[pos] = n;
        }
    }
    __syncthreads();
    if (tid == 0) {
        int minidx = si[0];
        g_assign[b]   = minidx;            // provisional (final if single cand)
        out_assign[b] = (float)minidx;
        if (scnt > 1) {
            int wi = atomicAdd(&g_nwork, 1);
            g_work[wi] = b;
            if (scnt <= NC_MAX) {
                g_ncand[b] = scnt;
                for (int c = 0; c < scnt; c++) g_cand[b][c] = scand[c];
            } else {
                g_ncand[b] = 0;            // sentinel: rescore all 512
            }
        }
    }
}

// ---------------- K3b: exact f64 rescore of flagged rows --------------------
__global__ __launch_bounds__(128) void k_rescore(const float* __restrict__ y,
                                                 const float* __restrict__ m,
                                                 float* __restrict__ out_assign) {
    int w = blockIdx.x;
    if (w >= g_nwork) return;
    int b  = g_work[w];
    int nc = g_ncand[b];
    int total = (nc == 0) ? NN : nc;
    int tid = threadIdx.x;
    const float* yrow = y + (size_t)b * KD;
    __shared__ double sred[128];
    __shared__ double sbestv;
    __shared__ int    sbesti;
    if (tid == 0) { sbestv = 1e300; sbesti = 0x7fffffff; }
    __syncthreads();
    for (int c = 0; c < total; c++) {
        int n = (nc == 0) ? c : g_cand[b][c];
        const float* mrow = m + (size_t)n * KD;
        double s = 0.0;
        for (int k = tid; k < KD; k += 128) {
            double mk = (double)mrow[k];
            s += mk * (mk - 2.0 * (double)yrow[k]);
        }
        sred[tid] = s;
        __syncthreads();
        for (int st = 64; st > 0; st >>= 1) {
            if (tid < st) sred[tid] += sred[tid + st];
            __syncthreads();
        }
        if (tid == 0) {
            double v = sred[0];
            if (v < sbestv || (v == sbestv && n < sbesti)) { sbestv = v; sbesti = n; }
        }
        __syncthreads();
    }
    if (tid == 0) {
        g_assign[b]   = sbesti;
        out_assign[b] = (float)sbesti;
    }
}

// ---------------- K4: stable per-centroid compaction (1 warp / centroid) ----
__global__ __launch_bounds__(32) void k_group(const float* __restrict__ p_in,
                                              float* __restrict__ p_out) {
    int z = blockIdx.x;
    int lane = threadIdx.x;
    int pos = 0;
    for (int c = 0; c < BB; c += 32) {
        int a = g_assign[c + lane];
        unsigned msk = __ballot_sync(0xffffffffu, a == z);
        if (a == z)
            g_items2[(size_t)z * BB + pos + __popc(msk & ((1u << lane) - 1))] = c + lane;
        pos += __popc(msk);
    }
    if (lane == 0) {
        g_cnt[z] = pos;
        p_out[z] = p_in[z] + (float)pos;
    }
}

// ---------------- K5: EMA chains, KD split 4-way + register prefetch --------
#define GCH 4
#define CHUNK (KD / GCH)   // 2048 floats = 512 float4; 256 thr x 2 float4

__global__ __launch_bounds__(256) void k_update(const float* __restrict__ Y,
                                                const float* __restrict__ Min,
                                                const float* __restrict__ SDin,
                                                float* __restrict__ out_m,
                                                float* __restrict__ out_sd) {
    int z   = blockIdx.x;
    int g   = blockIdx.y;
    int tid = threadIdx.x;
    const size_t base = (size_t)z * KD + (size_t)g * CHUNK;

    float4 mv[2], sv[2];
    const float4* mrow = (const float4*)(Min  + base);
    const float4* srow = (const float4*)(SDin + base);
#pragma unroll
    for (int t = 0; t < 2; t++) {
        mv[t] = mrow[tid + t * 256];
        sv[t] = srow[tid + t * 256];
    }
    int cnt = g_cnt[z];
    const int* items = g_items2 + (size_t)z * BB;

    float4 ycur[2], ynxt[2];
    if (cnt > 0) {
        const float4* yrow = (const float4*)(Y + (size_t)items[0] * KD + (size_t)g * CHUNK);
#pragma unroll
        for (int t = 0; t < 2; t++) ycur[t] = yrow[tid + t * 256];
    }
    for (int j = 0; j < cnt; j++) {
        if (j + 1 < cnt) {
            const float4* yrow = (const float4*)(Y + (size_t)items[j + 1] * KD + (size_t)g * CHUNK);
#pragma unroll
            for (int t = 0; t < 2; t++) ynxt[t] = yrow[tid + t * 256];
        }
#pragma unroll
        for (int t = 0; t < 2; t++) {
            float4 yv = ycur[t];
            float d;
            mv[t].x = mv[t].x * 0.001f + yv.x * 0.999f;
            d = mv[t].x - yv.x; sv[t].x = d * d * 0.001f + sv[t].x * 0.999f;
            mv[t].y = mv[t].y * 0.001f + yv.y * 0.999f;
            d = mv[t].y - yv.y; sv[t].y = d * d * 0.001f + sv[t].y * 0.999f;
            mv[t].z = mv[t].z * 0.001f + yv.z * 0.999f;
            d = mv[t].z - yv.z; sv[t].z = d * d * 0.001f + sv[t].z * 0.999f;
            mv[t].w = mv[t].w * 0.001f + yv.w * 0.999f;
            d = mv[t].w - yv.w; sv[t].w = d * d * 0.001f + sv[t].w * 0.999f;
        }
#pragma unroll
        for (int t = 0; t < 2; t++) ycur[t] = ynxt[t];
    }
    float4* mo = (float4*)(out_m  + base);
    float4* so = (float4*)(out_sd + base);
#pragma unroll
    for (int t = 0; t < 2; t++) {
        mo[tid + t * 256] = mv[t];
        so[tid + t * 256] = sv[t];
    }
}

// ---------------- launch ----------------------------------------------------
extern "C" void kernel_launch(void* const* d_in, const int* in_sizes, int n_in,
                              void* d_out, int out_size) {
    const float* y  = (const float*)d_in[0];
    const float* m  = (const float*)d_in[1];
    const float* sd = (const float*)d_in[2];
    const float* p  = (const float*)d_in[3];

    float* out      = (float*)d_out;
    float* out_m    = out;
    float* out_sd   = out + (size_t)NN * KD;
    float* out_p    = out + 2 * (size_t)NN * KD;
    float* out_asgn = out_p + NN;

    cudaFuncSetAttribute(k_gemm, cudaFuncAttributeMaxDynamicSharedMemorySize, SM_TOTAL);

    const int conv_blocks = (int)(((size_t)BB * KD + (size_t)NN * KD) / 8 / 256);
    k_convert<<<conv_blocks, 256>>>(y, m);
    k_sumsq<<<NN, 256>>>(m);
    dim3 grid(NN / 64, BB / 128, KSPL);
    k_gemm<<<grid, 256, SM_TOTAL>>>();
    k_argmin_cand<<<BB, 128>>>(out_asgn);
    k_rescore<<<BB, 128>>>(y, m, out_asgn);
    k_group<<<NN, 32>>>(p, out_p);
    dim3 ugrid(NN, GCH);
    k_update<<<ugrid, 256>>>(y, m, sd, out_m, out_sd);
}

// round 8
// speedup vs baseline: 4.2925x; 1.0634x over previous
#include <cuda_runtime.h>
#include <cuda_fp16.h>
#include <cstdint>

#define BB 2048   // batch
#define NN 512    // codebook
#define KD 8192   // C*T
#define NC_MAX 16
#define CAND_T 2.0f
#define KSPL 4
#define KPART (KD / KSPL)        // 2048

// ---------------- device scratch (no allocations allowed) -------------------
__device__ __half g_yh[(size_t)BB * KD];   // fp16 y
__device__ __half g_mh[(size_t)NN * KD];   // fp16 m
__device__ float g_part[KSPL][BB][NN];     // partial dots (16 MB)
__device__ float g_mm[NN];
__device__ int   g_assign[BB];
__device__ int   g_cnt[NN];
__device__ int   g_items2[(size_t)NN * BB];
__device__ int   g_nwork;
__device__ int   g_work[BB];
__device__ int   g_ncand[BB];              // 0 => all 512
__device__ int   g_cand[BB][NC_MAX];

// ---------------- PTX helpers (sm_80-level ISA only) ------------------------
__device__ __forceinline__ uint32_t smem_u32(const void* p) {
    uint32_t a;
    asm("{ .reg .u64 t; cvta.to.shared.u64 t, %1; cvt.u32.u64 %0, t; }" : "=r"(a) : "l"(p));
    return a;
}
__device__ __forceinline__ void cp_async16(uint32_t dst, const void* src) {
    asm volatile("cp.async.cg.shared.global [%0], [%1], 16;" :: "r"(dst), "l"(src));
}
__device__ __forceinline__ void ldm_x4(uint32_t* r, uint32_t addr) {
    asm volatile("ldmatrix.sync.aligned.m8n8.x4.shared.b16 {%0,%1,%2,%3}, [%4];"
                 : "=r"(r[0]), "=r"(r[1]), "=r"(r[2]), "=r"(r[3]) : "r"(addr));
}
__device__ __forceinline__ void mma_f16(float* d, const uint32_t* a, const uint32_t* b) {
    asm volatile(
        "mma.sync.aligned.m16n8k16.row.col.f32.f16.f16.f32 "
        "{%0,%1,%2,%3}, {%4,%5,%6,%7}, {%8,%9}, {%0,%1,%2,%3};"
        : "+f"(d[0]), "+f"(d[1]), "+f"(d[2]), "+f"(d[3])
        : "r"(a[0]), "r"(a[1]), "r"(a[2]), "r"(a[3]), "r"(b[0]), "r"(b[1]));
}

// ---------------- K0: fp32 -> fp16 ------------------------------------------
__global__ __launch_bounds__(256) void k_convert(const float* __restrict__ y,
                                                 const float* __restrict__ m) {
    if (blockIdx.x == 0 && threadIdx.x == 0) g_nwork = 0;
    const size_t YC = (size_t)BB * KD / 8;
    size_t gid = (size_t)blockIdx.x * 256 + threadIdx.x;
    const float* src;
    __half* dst;
    size_t e;
    if (gid < YC) { src = y; dst = g_yh; e = gid * 8; }
    else          { src = m; dst = g_mh; e = (gid - YC) * 8; }
    float4 v0 = *(const float4*)(src + e);
    float4 v1 = *(const float4*)(src + e + 4);
    float f[8] = {v0.x, v0.y, v0.z, v0.w, v1.x, v1.y, v1.z, v1.w};
    __half h[8];
#pragma unroll
    for (int i = 0; i < 8; i++) h[i] = __float2half_rn(f[i]);
    *(uint4*)(dst + e) = *(uint4*)h;
}

// ---------------- K1: sum-of-squares for m rows only ------------------------
__global__ __launch_bounds__(256) void k_sumsq(const float* __restrict__ m) {
    int r = blockIdx.x;
    const float4* row4 = (const float4*)(m + (size_t)r * KD);
    float s = 0.f;
    for (int i = threadIdx.x; i < KD / 4; i += 256) {
        float4 v = row4[i];
        s += v.x * v.x + v.y * v.y + v.z * v.z + v.w * v.w;
    }
    __shared__ float sh[256];
    sh[threadIdx.x] = s;
    __syncthreads();
    for (int st = 128; st > 0; st >>= 1) {
        if (threadIdx.x < st) sh[threadIdx.x] += sh[threadIdx.x + st];
        __syncthreads();
    }
    if (threadIdx.x == 0) g_mm[r] = sh[0];
}

// ---------------- K2: fp16 HMMA dot GEMM, K-split 4, 3 CTA/SM ---------------
// BM=128, BN=64, BK=64, 256 threads = 8 warps (4M x 2N), warp tile 32x32.
// smem rows padded to 144B -> conflict-free ldmatrix. DEPTH=2 (latency hidden
// laterally by 3 co-resident CTAs).
#define SROW 144
#define A_MAT (128 * SROW)       // 18432
#define B_MAT (64 * SROW)        // 9216
#define STG   (A_MAT + B_MAT)    // 27648
#define DEPTH 2
#define SM_TOTAL (DEPTH * STG)   // 55296
#define NSTAGES (KPART / 64)     // 32

__device__ __forceinline__ void load_stage(uint32_t sb, int buf, int b0, int n0, int k0,
                                           int tid) {
    uint32_t stA = sb + buf * STG;
    uint32_t stB = stA + A_MAT;
#pragma unroll
    for (int t = 0; t < 4; t++) {                 // A: 128 rows x 8 x 16B
        int idx = t * 256 + tid;
        int row = idx >> 3, ch = idx & 7;
        const void* src = g_yh + (size_t)(b0 + row) * KD + k0 + ch * 8;
        cp_async16(stA + row * SROW + ch * 16, src);
    }
#pragma unroll
    for (int t = 0; t < 2; t++) {                 // B: 64 rows x 8 x 16B
        int idx = t * 256 + tid;
        int row = idx >> 3, ch = idx & 7;
        const void* src = g_mh + (size_t)(n0 + row) * KD + k0 + ch * 8;
        cp_async16(stB + row * SROW + ch * 16, src);
    }
    asm volatile("cp.async.commit_group;");
}

__global__ __launch_bounds__(256, 3) void k_gemm() {
    extern __shared__ char smem[];
    const uint32_t sb = smem_u32(smem);
    const int tid = threadIdx.x;
    const int lane = tid & 31;
    const int wid = tid >> 5;
    const int wm = wid >> 1;          // 0..3 -> M offset wm*32
    const int wn = wid & 1;           // 0..1 -> N offset wn*32
    const int b0 = blockIdx.y * 128;
    const int n0 = blockIdx.x * 64;
    const int ks = blockIdx.z;
    const int kbase = ks * KPART;

    float acc[2][4][4];
#pragma unroll
    for (int i = 0; i < 2; i++)
#pragma unroll
        for (int j = 0; j < 4; j++)
#pragma unroll
            for (int c = 0; c < 4; c++) acc[i][j][c] = 0.f;

    load_stage(sb, 0, b0, n0, kbase, tid);

    for (int s = 0; s < NSTAGES; s++) {
        if (s + 1 < NSTAGES) {
            load_stage(sb, (s + 1) & 1, b0, n0, kbase + (s + 1) * 64, tid);
            asm volatile("cp.async.wait_group 1;" ::: "memory");
        } else {
            asm volatile("cp.async.wait_group 0;" ::: "memory");
        }
        __syncthreads();

        uint32_t stA = sb + (s & 1) * STG;
        uint32_t stB = stA + A_MAT;

#pragma unroll
        for (int kstep = 0; kstep < 4; kstep++) {
            uint32_t ah[2][4];
#pragma unroll
            for (int mt = 0; mt < 2; mt++) {
                int row = wm * 32 + mt * 16 + (lane & 15);
                int ch = kstep * 2 + (lane >> 4);
                ldm_x4(ah[mt], stA + row * SROW + ch * 16);
            }
            uint32_t bh[4][2];
#pragma unroll
            for (int p = 0; p < 2; p++) {
                int row = wn * 32 + p * 16 + (lane & 7) + (lane >> 4) * 8;
                int ch = kstep * 2 + ((lane >> 3) & 1);
                uint32_t r4[4];
                ldm_x4(r4, stB + row * SROW + ch * 16);
                bh[p * 2 + 0][0] = r4[0]; bh[p * 2 + 0][1] = r4[1];
                bh[p * 2 + 1][0] = r4[2]; bh[p * 2 + 1][1] = r4[3];
            }
#pragma unroll
            for (int mt = 0; mt < 2; mt++)
#pragma unroll
                for (int nt = 0; nt < 4; nt++)
                    mma_f16(acc[mt][nt], ah[mt], bh[nt]);
        }
        __syncthreads();
    }

    // epilogue: store partial dot for this K quarter
#pragma unroll
    for (int mt = 0; mt < 2; mt++) {
        int row0 = b0 + wm * 32 + mt * 16 + (lane >> 2);
        int row1 = row0 + 8;
#pragma unroll
        for (int nt = 0; nt < 4; nt++) {
            int col = n0 + wn * 32 + nt * 8 + (lane & 3) * 2;
            float2 v0, v1;
            v0.x = acc[mt][nt][0]; v0.y = acc[mt][nt][1];
            v1.x = acc[mt][nt][2]; v1.y = acc[mt][nt][3];
            *(float2*)(&g_part[ks][row0][col]) = v0;
            *(float2*)(&g_part[ks][row1][col]) = v1;
        }
    }
}

// ---------------- K3: combine partials, argmin + candidate collection -------
__global__ __launch_bounds__(128) void k_argmin_cand(float* __restrict__ out_assign) {
    int b = blockIdx.x;
    int tid = threadIdx.x;
    __shared__ float srow[NN];
    const float4* p0 = (const float4*)&g_part[0][b][0];
    const float4* p1 = (const float4*)&g_part[1][b][0];
    const float4* p2 = (const float4*)&g_part[2][b][0];
    const float4* p3 = (const float4*)&g_part[3][b][0];
    const float4* mm4 = (const float4*)g_mm;
    for (int i = tid; i < NN / 4; i += 128) {
        float4 a = p0[i], c = p1[i], d = p2[i], e = p3[i], mm = mm4[i];
        float4 r;
        r.x = mm.x - 2.0f * ((a.x + c.x) + (d.x + e.x));
        r.y = mm.y - 2.0f * ((a.y + c.y) + (d.y + e.y));
        r.z = mm.z - 2.0f * ((a.z + c.z) + (d.z + e.z));
        r.w = mm.w - 2.0f * ((a.w + c.w) + (d.w + e.w));
        *(float4*)&srow[i * 4] = r;
    }
    __syncthreads();

    float best = 3.4e38f;
    int   bi = 0;
    for (int n = tid; n < NN; n += 128) {
        float v = srow[n];
        if (v < best) { best = v; bi = n; }
    }
    __shared__ float sv[128];
    __shared__ int   si[128];
    sv[tid] = best;
    si[tid] = bi;
    __syncthreads();
    for (int st = 64; st > 0; st >>= 1) {
        if (tid < st) {
            float v2 = sv[tid + st];
            int   i2 = si[tid + st];
            if (v2 < sv[tid] || (v2 == sv[tid] && i2 < si[tid])) {
                sv[tid] = v2;
                si[tid] = i2;
            }
        }
        __syncthreads();
    }
    __shared__ int scnt;
    __shared__ int scand[NC_MAX];
    if (tid == 0) scnt = 0;
    __syncthreads();
    float thr = sv[0] + CAND_T;
    for (int n = tid; n < NN; n += 128) {
        if (srow[n] <= thr) {
            int pos = atomicAdd(&scnt, 1);
            if (pos < NC_MAX) scand[pos] = n;
        }
    }
    __syncthreads();
    if (tid == 0) {
        int minidx = si[0];
        g_assign[b]   = minidx;            // provisional (final if single cand)
        out_assign[b] = (float)minidx;
        if (scnt > 1) {
            int wi = atomicAdd(&g_nwork, 1);
            g_work[wi] = b;
            if (scnt <= NC_MAX) {
                g_ncand[b] = scnt;
                for (int c = 0; c < scnt; c++) g_cand[b][c] = scand[c];
            } else {
                g_ncand[b] = 0;            // sentinel: rescore all 512
            }
        }
    }
}

// ---------------- K3b: exact f64 rescore of flagged rows --------------------
__global__ __launch_bounds__(128) void k_rescore(const float* __restrict__ y,
                                                 const float* __restrict__ m,
                                                 float* __restrict__ out_assign) {
    int w = blockIdx.x;
    if (w >= g_nwork) return;
    int b  = g_work[w];
    int nc = g_ncand[b];
    int total = (nc == 0) ? NN : nc;
    int tid = threadIdx.x;
    const float* yrow = y + (size_t)b * KD;
    __shared__ double sred[128];
    __shared__ double sbestv;
    __shared__ int    sbesti;
    if (tid == 0) { sbestv = 1e300; sbesti = 0x7fffffff; }
    __syncthreads();
    for (int c = 0; c < total; c++) {
        int n = (nc == 0) ? c : g_cand[b][c];
        const float* mrow = m + (size_t)n * KD;
        double s = 0.0;
        for (int k = tid; k < KD; k += 128) {
            double mk = (double)mrow[k];
            s += mk * (mk - 2.0 * (double)yrow[k]);
        }
        sred[tid] = s;
        __syncthreads();
        for (int st = 64; st > 0; st >>= 1) {
            if (tid < st) sred[tid] += sred[tid + st];
            __syncthreads();
        }
        if (tid == 0) {
            double v = sred[0];
            if (v < sbestv || (v == sbestv && n < sbesti)) { sbestv = v; sbesti = n; }
        }
        __syncthreads();
    }
    if (tid == 0) {
        g_assign[b]   = sbesti;
        out_assign[b] = (float)sbesti;
    }
}

// ---------------- K4: stable per-centroid compaction (1 warp / centroid) ----
__global__ __launch_bounds__(32) void k_group(const float* __restrict__ p_in,
                                              float* __restrict__ p_out) {
    int z = blockIdx.x;
    int lane = threadIdx.x;
    int pos = 0;
    for (int c = 0; c < BB; c += 32) {
        int a = g_assign[c + lane];
        unsigned msk = __ballot_sync(0xffffffffu, a == z);
        if (a == z)
            g_items2[(size_t)z * BB + pos + __popc(msk & ((1u << lane) - 1))] = c + lane;
        pos += __popc(msk);
    }
    if (lane == 0) {
        g_cnt[z] = pos;
        p_out[z] = p_in[z] + (float)pos;
    }
}

// ---------------- K5: EMA chains, KD split 8-way + register prefetch --------
#define GCH 8
#define CHUNK (KD / GCH)   // 1024 floats = 256 float4; 256 thr x 1 float4

__global__ __launch_bounds__(256) void k_update(const float* __restrict__ Y,
                                                const float* __restrict__ Min,
                                                const float* __restrict__ SDin,
                                                float* __restrict__ out_m,
                                                float* __restrict__ out_sd) {
    int z   = blockIdx.x;
    int g   = blockIdx.y;
    int tid = threadIdx.x;
    const size_t base = (size_t)z * KD + (size_t)g * CHUNK;

    float4 mv = ((const float4*)(Min  + base))[tid];
    float4 sv = ((const float4*)(SDin + base))[tid];
    int cnt = g_cnt[z];
    const int* items = g_items2 + (size_t)z * BB;

    float4 ycur, ynxt;
    if (cnt > 0)
        ycur = ((const float4*)(Y + (size_t)items[0] * KD + (size_t)g * CHUNK))[tid];
    for (int j = 0; j < cnt; j++) {
        if (j + 1 < cnt)
            ynxt = ((const float4*)(Y + (size_t)items[j + 1] * KD + (size_t)g * CHUNK))[tid];
        float4 yv = ycur;
        float d;
        mv.x = mv.x * 0.001f + yv.x * 0.999f;
        d = mv.x - yv.x; sv.x = d * d * 0.001f + sv.x * 0.999f;
        mv.y = mv.y * 0.001f + yv.y * 0.999f;
        d = mv.y - yv.y; sv.y = d * d * 0.001f + sv.y * 0.999f;
        mv.z = mv.z * 0.001f + yv.z * 0.999f;
        d = mv.z - yv.z; sv.z = d * d * 0.001f + sv.z * 0.999f;
        mv.w = mv.w * 0.001f + yv.w * 0.999f;
        d = mv.w - yv.w; sv.w = d * d * 0.001f + sv.w * 0.999f;
        ycur = ynxt;
    }
    ((float4*)(out_m  + base))[tid] = mv;
    ((float4*)(out_sd + base))[tid] = sv;
}

// ---------------- launch ----------------------------------------------------
extern "C" void kernel_launch(void* const* d_in, const int* in_sizes, int n_in,
                              void* d_out, int out_size) {
    const float* y  = (const float*)d_in[0];
    const float* m  = (const float*)d_in[1];
    const float* sd = (const float*)d_in[2];
    const float* p  = (const float*)d_in[3];

    float* out      = (float*)d_out;
    float* out_m    = out;
    float* out_sd   = out + (size_t)NN * KD;
    float* out_p    = out + 2 * (size_t)NN * KD;
    float* out_asgn = out_p + NN;

    cudaFuncSetAttribute(k_gemm, cudaFuncAttributeMaxDynamicSharedMemorySize, SM_TOTAL);

    const int conv_blocks = (int)(((size_t)BB * KD + (size_t)NN * KD) / 8 / 256);
    k_convert<<<conv_blocks, 256>>>(y, m);
    k_sumsq<<<NN, 256>>>(m);
    dim3 grid(NN / 64, BB / 128, KSPL);
    k_gemm<<<grid, 256, SM_TOTAL>>>();
    k_argmin_cand<<<BB, 128>>>(out_asgn);
    k_rescore<<<BB, 128>>>(y, m, out_asgn);
    k_group<<<NN, 32>>>(p, out_p);
    dim3 ugrid(NN, GCH);
    k_update<<<ugrid, 256>>>(y, m, sd, out_m, out_sd);
}

// round 9
// speedup vs baseline: 4.3094x; 1.0039x over previous
#include <cuda_runtime.h>
#include <cuda_fp16.h>
#include <cstdint>

#define BB 2048   // batch
#define NN 512    // codebook
#define KD 8192   // C*T
#define NC_MAX 16
#define CAND_T 4.0f
#define KSPL 4
#define KPART (KD / KSPL)        // 2048

// ---------------- device scratch (no allocations allowed) -------------------
__device__ __half g_yh[(size_t)BB * KD];   // fp16 y
__device__ __half g_mh[(size_t)NN * KD];   // fp16 m
__device__ float g_part[KSPL][BB][NN];     // partial dots (16 MB)
__device__ float g_mm[NN];
__device__ int   g_assign[BB];
__device__ int   g_cnt[NN];
__device__ int   g_items2[(size_t)NN * BB];
__device__ int   g_nwork;
__device__ int   g_work[BB];
__device__ int   g_ncand[BB];              // 0 => all 512
__device__ int   g_cand[BB][NC_MAX];

// ---------------- PTX helpers (sm_80-level ISA only) ------------------------
__device__ __forceinline__ uint32_t smem_u32(const void* p) {
    uint32_t a;
    asm("{ .reg .u64 t; cvta.to.shared.u64 t, %1; cvt.u32.u64 %0, t; }" : "=r"(a) : "l"(p));
    return a;
}
__device__ __forceinline__ void cp_async16(uint32_t dst, const void* src) {
    asm volatile("cp.async.cg.shared.global [%0], [%1], 16;" :: "r"(dst), "l"(src));
}
__device__ __forceinline__ void ldm_x4(uint32_t* r, uint32_t addr) {
    asm volatile("ldmatrix.sync.aligned.m8n8.x4.shared.b16 {%0,%1,%2,%3}, [%4];"
                 : "=r"(r[0]), "=r"(r[1]), "=r"(r[2]), "=r"(r[3]) : "r"(addr));
}
// f16-accumulator HMMA (2x rate vs f32 acc)
__device__ __forceinline__ void mma_f16a(uint32_t* d, const uint32_t* a, const uint32_t* b) {
    asm volatile(
        "mma.sync.aligned.m16n8k16.row.col.f16.f16.f16.f16 "
        "{%0,%1}, {%2,%3,%4,%5}, {%6,%7}, {%0,%1};"
        : "+r"(d[0]), "+r"(d[1])
        : "r"(a[0]), "r"(a[1]), "r"(a[2]), "r"(a[3]), "r"(b[0]), "r"(b[1]));
}

// ---------------- K0: fp32 -> fp16 ------------------------------------------
__global__ __launch_bounds__(256) void k_convert(const float* __restrict__ y,
                                                 const float* __restrict__ m) {
    if (blockIdx.x == 0 && threadIdx.x == 0) g_nwork = 0;
    const size_t YC = (size_t)BB * KD / 8;
    size_t gid = (size_t)blockIdx.x * 256 + threadIdx.x;
    const float* src;
    __half* dst;
    size_t e;
    if (gid < YC) { src = y; dst = g_yh; e = gid * 8; }
    else          { src = m; dst = g_mh; e = (gid - YC) * 8; }
    float4 v0 = *(const float4*)(src + e);
    float4 v1 = *(const float4*)(src + e + 4);
    float f[8] = {v0.x, v0.y, v0.z, v0.w, v1.x, v1.y, v1.z, v1.w};
    __half h[8];
#pragma unroll
    for (int i = 0; i < 8; i++) h[i] = __float2half_rn(f[i]);
    *(uint4*)(dst + e) = *(uint4*)h;
}

// ---------------- K1: sum-of-squares for m rows only ------------------------
__global__ __launch_bounds__(256) void k_sumsq(const float* __restrict__ m) {
    int r = blockIdx.x;
    const float4* row4 = (const float4*)(m + (size_t)r * KD);
    float s = 0.f;
    for (int i = threadIdx.x; i < KD / 4; i += 256) {
        float4 v = row4[i];
        s += v.x * v.x + v.y * v.y + v.z * v.z + v.w * v.w;
    }
    __shared__ float sh[256];
    sh[threadIdx.x] = s;
    __syncthreads();
    for (int st = 128; st > 0; st >>= 1) {
        if (threadIdx.x < st) sh[threadIdx.x] += sh[threadIdx.x + st];
        __syncthreads();
    }
    if (threadIdx.x == 0) g_mm[r] = sh[0];
}

// ---------------- K2: fp16 HMMA (f16 acc) dot GEMM, K-split 4, 3 CTA/SM -----
// BM=128, BN=64, BK=64, 256 threads = 8 warps (4M x 2N), warp tile 32x32.
#define SROW 144
#define A_MAT (128 * SROW)       // 18432
#define B_MAT (64 * SROW)        // 9216
#define STG   (A_MAT + B_MAT)    // 27648
#define DEPTH 2
#define SM_TOTAL (DEPTH * STG)   // 55296
#define NSTAGES (KPART / 64)     // 32

__device__ __forceinline__ void load_stage(uint32_t sb, int buf, int b0, int n0, int k0,
                                           int tid) {
    uint32_t stA = sb + buf * STG;
    uint32_t stB = stA + A_MAT;
#pragma unroll
    for (int t = 0; t < 4; t++) {                 // A: 128 rows x 8 x 16B
        int idx = t * 256 + tid;
        int row = idx >> 3, ch = idx & 7;
        const void* src = g_yh + (size_t)(b0 + row) * KD + k0 + ch * 8;
        cp_async16(stA + row * SROW + ch * 16, src);
    }
#pragma unroll
    for (int t = 0; t < 2; t++) {                 // B: 64 rows x 8 x 16B
        int idx = t * 256 + tid;
        int row = idx >> 3, ch = idx & 7;
        const void* src = g_mh + (size_t)(n0 + row) * KD + k0 + ch * 8;
        cp_async16(stB + row * SROW + ch * 16, src);
    }
    asm volatile("cp.async.commit_group;");
}

__global__ __launch_bounds__(256, 3) void k_gemm() {
    extern __shared__ char smem[];
    const uint32_t sb = smem_u32(smem);
    const int tid = threadIdx.x;
    const int lane = tid & 31;
    const int wid = tid >> 5;
    const int wm = wid >> 1;          // 0..3 -> M offset wm*32
    const int wn = wid & 1;           // 0..1 -> N offset wn*32
    const int b0 = blockIdx.y * 128;
    const int n0 = blockIdx.x * 64;
    const int ks = blockIdx.z;
    const int kbase = ks * KPART;

    uint32_t acc[2][4][2];            // packed f16x2 accumulators
#pragma unroll
    for (int i = 0; i < 2; i++)
#pragma unroll
        for (int j = 0; j < 4; j++) { acc[i][j][0] = 0u; acc[i][j][1] = 0u; }

    load_stage(sb, 0, b0, n0, kbase, tid);

    for (int s = 0; s < NSTAGES; s++) {
        if (s + 1 < NSTAGES) {
            load_stage(sb, (s + 1) & 1, b0, n0, kbase + (s + 1) * 64, tid);
            asm volatile("cp.async.wait_group 1;" ::: "memory");
        } else {
            asm volatile("cp.async.wait_group 0;" ::: "memory");
        }
        __syncthreads();

        uint32_t stA = sb + (s & 1) * STG;
        uint32_t stB = stA + A_MAT;

#pragma unroll
        for (int kstep = 0; kstep < 4; kstep++) {
            uint32_t ah[2][4];
#pragma unroll
            for (int mt = 0; mt < 2; mt++) {
                int row = wm * 32 + mt * 16 + (lane & 15);
                int ch = kstep * 2 + (lane >> 4);
                ldm_x4(ah[mt], stA + row * SROW + ch * 16);
            }
            uint32_t bh[4][2];
#pragma unroll
            for (int p = 0; p < 2; p++) {
                int row = wn * 32 + p * 16 + (lane & 7) + (lane >> 4) * 8;
                int ch = kstep * 2 + ((lane >> 3) & 1);
                uint32_t r4[4];
                ldm_x4(r4, stB + row * SROW + ch * 16);
                bh[p * 2 + 0][0] = r4[0]; bh[p * 2 + 0][1] = r4[1];
                bh[p * 2 + 1][0] = r4[2]; bh[p * 2 + 1][1] = r4[3];
            }
#pragma unroll
            for (int mt = 0; mt < 2; mt++)
#pragma unroll
                for (int nt = 0; nt < 4; nt++)
                    mma_f16a(acc[mt][nt], ah[mt], bh[nt]);
        }
        __syncthreads();
    }

    // epilogue: unpack f16 partials -> fp32, store for this K quarter
#pragma unroll
    for (int mt = 0; mt < 2; mt++) {
        int row0 = b0 + wm * 32 + mt * 16 + (lane >> 2);
        int row1 = row0 + 8;
#pragma unroll
        for (int nt = 0; nt < 4; nt++) {
            int col = n0 + wn * 32 + nt * 8 + (lane & 3) * 2;
            __half2 h0 = *(__half2*)&acc[mt][nt][0];   // row r : (c, c+1)
            __half2 h1 = *(__half2*)&acc[mt][nt][1];   // row r+8: (c, c+1)
            float2 v0, v1;
            v0.x = __low2float(h0);  v0.y = __high2float(h0);
            v1.x = __low2float(h1);  v1.y = __high2float(h1);
            *(float2*)(&g_part[ks][row0][col]) = v0;
            *(float2*)(&g_part[ks][row1][col]) = v1;
        }
    }
}

// ---------------- K3: combine partials, argmin + candidate collection -------
__global__ __launch_bounds__(128) void k_argmin_cand(float* __restrict__ out_assign) {
    int b = blockIdx.x;
    int tid = threadIdx.x;
    __shared__ float srow[NN];
    const float4* p0 = (const float4*)&g_part[0][b][0];
    const float4* p1 = (const float4*)&g_part[1][b][0];
    const float4* p2 = (const float4*)&g_part[2][b][0];
    const float4* p3 = (const float4*)&g_part[3][b][0];
    const float4* mm4 = (const float4*)g_mm;
    for (int i = tid; i < NN / 4; i += 128) {
        float4 a = p0[i], c = p1[i], d = p2[i], e = p3[i], mm = mm4[i];
        float4 r;
        r.x = mm.x - 2.0f * ((a.x + c.x) + (d.x + e.x));
        r.y = mm.y - 2.0f * ((a.y + c.y) + (d.y + e.y));
        r.z = mm.z - 2.0f * ((a.z + c.z) + (d.z + e.z));
        r.w = mm.w - 2.0f * ((a.w + c.w) + (d.w + e.w));
        *(float4*)&srow[i * 4] = r;
    }
    __syncthreads();

    float best = 3.4e38f;
    int   bi = 0;
    for (int n = tid; n < NN; n += 128) {
        float v = srow[n];
        if (v < best) { best = v; bi = n; }
    }
    __shared__ float sv[128];
    __shared__ int   si[128];
    sv[tid] = best;
    si[tid] = bi;
    __syncthreads();
    for (int st = 64; st > 0; st >>= 1) {
        if (tid < st) {
            float v2 = sv[tid + st];
            int   i2 = si[tid + st];
            if (v2 < sv[tid] || (v2 == sv[tid] && i2 < si[tid])) {
                sv[tid] = v2;
                si[tid] = i2;
            }
        }
        __syncthreads();
    }
    __shared__ int scnt;
    __shared__ int scand[NC_MAX];
    if (tid == 0) scnt = 0;
    __syncthreads();
    float thr = sv[0] + CAND_T;
    for (int n = tid; n < NN; n += 128) {
        if (srow[n] <= thr) {
            int pos = atomicAdd(&scnt, 1);
            if (pos < NC_MAX) scand[pos] = n;
        }
    }
    __syncthreads();
    if (tid == 0) {
        int minidx = si[0];
        g_assign[b]   = minidx;            // provisional (final if single cand)
        out_assign[b] = (float)minidx;
        if (scnt > 1) {
            int wi = atomicAdd(&g_nwork, 1);
            g_work[wi] = b;
            if (scnt <= NC_MAX) {
                g_ncand[b] = scnt;
                for (int c = 0; c < scnt; c++) g_cand[b][c] = scand[c];
            } else {
                g_ncand[b] = 0;            // sentinel: rescore all 512
            }
        }
    }
}

// ---------------- K3b: exact f64 rescore of flagged rows --------------------
__global__ __launch_bounds__(128) void k_rescore(const float* __restrict__ y,
                                                 const float* __restrict__ m,
                                                 float* __restrict__ out_assign) {
    int w = blockIdx.x;
    if (w >= g_nwork) return;
    int b  = g_work[w];
    int nc = g_ncand[b];
    int total = (nc == 0) ? NN : nc;
    int tid = threadIdx.x;
    const float* yrow = y + (size_t)b * KD;
    __shared__ double sred[128];
    __shared__ double sbestv;
    __shared__ int    sbesti;
    if (tid == 0) { sbestv = 1e300; sbesti = 0x7fffffff; }
    __syncthreads();
    for (int c = 0; c < total; c++) {
        int n = (nc == 0) ? c : g_cand[b][c];
        const float* mrow = m + (size_t)n * KD;
        double s = 0.0;
        for (int k = tid; k < KD; k += 128) {
            double mk = (double)mrow[k];
            s += mk * (mk - 2.0 * (double)yrow[k]);
        }
        sred[tid] = s;
        __syncthreads();
        for (int st = 64; st > 0; st >>= 1) {
            if (tid < st) sred[tid] += sred[tid + st];
            __syncthreads();
        }
        if (tid == 0) {
            double v = sred[0];
            if (v < sbestv || (v == sbestv && n < sbesti)) { sbestv = v; sbesti = n; }
        }
        __syncthreads();
    }
    if (tid == 0) {
        g_assign[b]   = sbesti;
        out_assign[b] = (float)sbesti;
    }
}

// ---------------- K4: stable per-centroid compaction (1 warp / centroid) ----
__global__ __launch_bounds__(32) void k_group(const float* __restrict__ p_in,
                                              float* __restrict__ p_out) {
    int z = blockIdx.x;
    int lane = threadIdx.x;
    int pos = 0;
    for (int c = 0; c < BB; c += 32) {
        int a = g_assign[c + lane];
        unsigned msk = __ballot_sync(0xffffffffu, a == z);
        if (a == z)
            g_items2[(size_t)z * BB + pos + __popc(msk & ((1u << lane) - 1))] = c + lane;
        pos += __popc(msk);
    }
    if (lane == 0) {
        g_cnt[z] = pos;
        p_out[z] = p_in[z] + (float)pos;
    }
}

// ---------------- K5: EMA chains, KD split 8-way + register prefetch --------
#define GCH 8
#define CHUNK (KD / GCH)   // 1024 floats = 256 float4; 256 thr x 1 float4

__global__ __launch_bounds__(256) void k_update(const float* __restrict__ Y,
                                                const float* __restrict__ Min,
                                                const float* __restrict__ SDin,
                                                float* __restrict__ out_m,
                                                float* __restrict__ out_sd) {
    int z   = blockIdx.x;
    int g   = blockIdx.y;
    int tid = threadIdx.x;
    const size_t base = (size_t)z * KD + (size_t)g * CHUNK;

    float4 mv = ((const float4*)(Min  + base))[tid];
    float4 sv = ((const float4*)(SDin + base))[tid];
    int cnt = g_cnt[z];
    const int* items = g_items2 + (size_t)z * BB;

    float4 ycur, ynxt;
    if (cnt > 0)
        ycur = ((const float4*)(Y + (size_t)items[0] * KD + (size_t)g * CHUNK))[tid];
    for (int j = 0; j < cnt; j++) {
        if (j + 1 < cnt)
            ynxt = ((const float4*)(Y + (size_t)items[j + 1] * KD + (size_t)g * CHUNK))[tid];
        float4 yv = ycur;
        float d;
        mv.x = mv.x * 0.001f + yv.x * 0.999f;
        d = mv.x - yv.x; sv.x = d * d * 0.001f + sv.x * 0.999f;
        mv.y = mv.y * 0.001f + yv.y * 0.999f;
        d = mv.y - yv.y; sv.y = d * d * 0.001f + sv.y * 0.999f;
        mv.z = mv.z * 0.001f + yv.z * 0.999f;
        d = mv.z - yv.z; sv.z = d * d * 0.001f + sv.z * 0.999f;
        mv.w = mv.w * 0.001f + yv.w * 0.999f;
        d = mv.w - yv.w; sv.w = d * d * 0.001f + sv.w * 0.999f;
        ycur = ynxt;
    }
    ((float4*)(out_m  + base))[tid] = mv;
    ((float4*)(out_sd + base))[tid] = sv;
}

// ---------------- launch ----------------------------------------------------
extern "C" void kernel_launch(void* const* d_in, const int* in_sizes, int n_in,
                              void* d_out, int out_size) {
    const float* y  = (const float*)d_in[0];
    const float* m  = (const float*)d_in[1];
    const float* sd = (const float*)d_in[2];
    const float* p  = (const float*)d_in[3];

    float* out      = (float*)d_out;
    float* out_m    = out;
    float* out_sd   = out + (size_t)NN * KD;
    float* out_p    = out + 2 * (size_t)NN * KD;
    float* out_asgn = out_p + NN;

    cudaFuncSetAttribute(k_gemm, cudaFuncAttributeMaxDynamicSharedMemorySize, SM_TOTAL);

    const int conv_blocks = (int)(((size_t)BB * KD + (size_t)NN * KD) / 8 / 256);
    k_convert<<<conv_blocks, 256>>>(y, m);
    k_sumsq<<<NN, 256>>>(m);
    dim3 grid(NN / 64, BB / 128, KSPL);
    k_gemm<<<grid, 256, SM_TOTAL>>>();
    k_argmin_cand<<<BB, 128>>>(out_asgn);
    k_rescore<<<BB, 128>>>(y, m, out_asgn);
    k_group<<<NN, 32>>>(p, out_p);
    dim3 ugrid(NN, GCH);
    k_update<<<ugrid, 256>>>(y, m, sd, out_m, out_sd);
}